// round 3
// baseline (speedup 1.0000x reference)
#include <cuda_runtime.h>
#include <cuda_bf16.h>

// ---------------------------------------------------------------------------
// MultiheadSelfAttention: B=2, N=2048, D=1024, H=16, hd=64, fp32.
//   Q/K/V = x @ W^T + b   (written head-transposed [B,H,N,64] to scratch)
//   flash attention per (b,h) with mask (scores masked -> -20000)
//   out = Attn @ Wo^T + bo
// Scratch lives in __device__ globals (no allocations anywhere).
// ---------------------------------------------------------------------------

#define BATCH   2
#define SEQ     2048
#define DIM     1024
#define HEADS   16
#define HDIM    64
#define MROWS   (BATCH * SEQ)            // 4096

__device__ float g_Q[BATCH * HEADS * SEQ * HDIM];    // 16 MB
__device__ float g_K[BATCH * HEADS * SEQ * HDIM];    // 16 MB
__device__ float g_V[BATCH * HEADS * SEQ * HDIM];    // 16 MB
__device__ float g_Att[MROWS * DIM];                 // 16 MB

// ---------------------------------------------------------------------------
// GEMM: C[m][n] = sum_k X[m][k] * W[n][k] + bias[n]
// M=4096, N=1024, K=1024.  Tile 128x128x16, 256 threads, 8x8 micro (stride-16
// interleaved ownership -> conflict-free smem compute loads with stride 17).
// mode 0/1/2: X = Xp (input x), write g_Q/g_K/g_V head-transposed.
// mode 3:     X = g_Att,        write Cp plain row-major.
// ---------------------------------------------------------------------------
__global__ __launch_bounds__(256, 2)
void gemm4096(const float* __restrict__ Xp,
              const float* __restrict__ W,
              const float* __restrict__ bias,
              float* __restrict__ Cp,
              int mode)
{
    __shared__ float Xs[128][17];
    __shared__ float Ws[128][17];

    const float* X = (mode == 3) ? g_Att : Xp;

    const int tid = threadIdx.x;
    const int m0  = blockIdx.y << 7;
    const int n0  = blockIdx.x << 7;
    const int tr  = tid >> 4;        // 0..15
    const int tc  = tid & 15;        // 0..15
    const int lrow = tid >> 2;       // 0..63
    const int lc   = (tid & 3) << 2; // 0,4,8,12

    float acc[8][8];
#pragma unroll
    for (int i = 0; i < 8; i++)
#pragma unroll
        for (int j = 0; j < 8; j++) acc[i][j] = 0.f;

    const float* Xg = X + (size_t)(m0 + lrow) * DIM + lc;
    const float* Wg = W + (size_t)(n0 + lrow) * DIM + lc;

    for (int k0 = 0; k0 < DIM; k0 += 16) {
        float4 x0 = *(const float4*)(Xg + k0);
        float4 x1 = *(const float4*)(Xg + (size_t)64 * DIM + k0);
        float4 w0 = *(const float4*)(Wg + k0);
        float4 w1 = *(const float4*)(Wg + (size_t)64 * DIM + k0);

        Xs[lrow][lc + 0] = x0.x; Xs[lrow][lc + 1] = x0.y;
        Xs[lrow][lc + 2] = x0.z; Xs[lrow][lc + 3] = x0.w;
        Xs[lrow + 64][lc + 0] = x1.x; Xs[lrow + 64][lc + 1] = x1.y;
        Xs[lrow + 64][lc + 2] = x1.z; Xs[lrow + 64][lc + 3] = x1.w;
        Ws[lrow][lc + 0] = w0.x; Ws[lrow][lc + 1] = w0.y;
        Ws[lrow][lc + 2] = w0.z; Ws[lrow][lc + 3] = w0.w;
        Ws[lrow + 64][lc + 0] = w1.x; Ws[lrow + 64][lc + 1] = w1.y;
        Ws[lrow + 64][lc + 2] = w1.z; Ws[lrow + 64][lc + 3] = w1.w;
        __syncthreads();

#pragma unroll
        for (int k = 0; k < 16; k++) {
            float a[8], b[8];
#pragma unroll
            for (int i = 0; i < 8; i++) a[i] = Xs[tr + 16 * i][k];
#pragma unroll
            for (int j = 0; j < 8; j++) b[j] = Ws[tc + 16 * j][k];
#pragma unroll
            for (int i = 0; i < 8; i++)
#pragma unroll
                for (int j = 0; j < 8; j++)
                    acc[i][j] = fmaf(a[i], b[j], acc[i][j]);
        }
        __syncthreads();
    }

    float bb[8];
#pragma unroll
    for (int j = 0; j < 8; j++) bb[j] = bias[n0 + tc + 16 * j];

    if (mode == 3) {
#pragma unroll
        for (int i = 0; i < 8; i++) {
            const int m = m0 + tr + 16 * i;
#pragma unroll
            for (int j = 0; j < 8; j++) {
                const int n = n0 + tc + 16 * j;
                Cp[(size_t)m * DIM + n] = acc[i][j] + bb[j];
            }
        }
    } else {
        float* O = (mode == 0) ? g_Q : (mode == 1) ? g_K : g_V;
        const int bidx = m0 >> 11;           // whole tile shares batch
#pragma unroll
        for (int i = 0; i < 8; i++) {
            const int m  = m0 + tr + 16 * i;
            const int nn = m & (SEQ - 1);
#pragma unroll
            for (int j = 0; j < 8; j++) {
                const int n  = n0 + tc + 16 * j;
                const int h  = n >> 6;
                const int dh = n & 63;
                O[(size_t)((bidx << 4) + h) * (SEQ * HDIM) + (size_t)nn * HDIM + dh]
                    = acc[i][j] + bb[j];
            }
        }
    }
}

// ---------------------------------------------------------------------------
// Flash attention. One block = (b, h, qtile of 64). 256 threads.
// S = (Q*0.125) @ K^T  (4x4-micro GEMM) -> Ss smem -> online softmax
// (row-ownership: 4 lanes per row, shfl reductions) -> O += P @ V (4x4 GEMM).
// smem stride 65 keeps every access pattern conflict-free.
// ---------------------------------------------------------------------------
#define AST 65
#define ATTN_SMEM ((4 * 64 * AST + 128) * (int)sizeof(float))   // 67072 B

__global__ __launch_bounds__(256, 2)
void attn64(const unsigned char* __restrict__ mask)
{
    extern __shared__ float sm[];
    float* Qs   = sm;                 // 64*65
    float* Ks   = Qs + 64 * AST;      // 64*65
    float* Vs   = Ks + 64 * AST;      // 64*65
    float* Ss   = Vs + 64 * AST;      // 64*65
    float* alph = Ss + 64 * AST;      // 64
    float* mfl  = alph + 64;          // 64

    const int b  = blockIdx.z;
    const int h  = blockIdx.y;
    const int qt = blockIdx.x;
    const int tid = threadIdx.x;

    const size_t bh = (size_t)((b << 4) + h) * (SEQ * HDIM);
    const float* Qg = g_Q + bh + (size_t)(qt << 6) * HDIM;
    const float* Kg = g_K + bh;
    const float* Vg = g_V + bh;
    const unsigned char* mg = mask + b * SEQ;

    const int lrow = tid >> 2;         // 0..63
    const int lc   = (tid & 3) << 4;   // 0,16,32,48
    const int tr   = tid >> 4;         // 0..15 (gemm rows)
    const int tc   = tid & 15;         // 0..15 (gemm cols)
    const int r    = tid >> 2;         // softmax row
    const int q    = tid & 3;          // softmax lane-in-row

    // load Q tile, pre-scaled by 1/sqrt(64)
#pragma unroll
    for (int c = 0; c < 16; c += 4) {
        float4 v = *(const float4*)(Qg + lrow * HDIM + lc + c);
        Qs[lrow * AST + lc + c + 0] = v.x * 0.125f;
        Qs[lrow * AST + lc + c + 1] = v.y * 0.125f;
        Qs[lrow * AST + lc + c + 2] = v.z * 0.125f;
        Qs[lrow * AST + lc + c + 3] = v.w * 0.125f;
    }

    float m_run = -1e30f, l_run = 0.f;
    float acc[4][4];
#pragma unroll
    for (int i = 0; i < 4; i++)
#pragma unroll
        for (int j = 0; j < 4; j++) acc[i][j] = 0.f;

    for (int kt = 0; kt < SEQ / 64; kt++) {
        __syncthreads();   // protect Ks/Vs/Ss reuse from previous iteration

        const float* Kt = Kg + (size_t)(kt << 6) * HDIM;
        const float* Vt = Vg + (size_t)(kt << 6) * HDIM;
#pragma unroll
        for (int c = 0; c < 16; c += 4) {
            float4 kv = *(const float4*)(Kt + lrow * HDIM + lc + c);
            Ks[lrow * AST + lc + c + 0] = kv.x;
            Ks[lrow * AST + lc + c + 1] = kv.y;
            Ks[lrow * AST + lc + c + 2] = kv.z;
            Ks[lrow * AST + lc + c + 3] = kv.w;
            float4 vv = *(const float4*)(Vt + lrow * HDIM + lc + c);
            Vs[lrow * AST + lc + c + 0] = vv.x;
            Vs[lrow * AST + lc + c + 1] = vv.y;
            Vs[lrow * AST + lc + c + 2] = vv.z;
            Vs[lrow * AST + lc + c + 3] = vv.w;
        }
        if (tid < 64) mfl[tid] = mg[(kt << 6) + tid] ? 1.f : 0.f;
        __syncthreads();

        // S = Qs @ Ks^T (each thread 4x4, interleaved stride-16 ownership)
        float sacc[4][4];
#pragma unroll
        for (int i = 0; i < 4; i++)
#pragma unroll
            for (int j = 0; j < 4; j++) sacc[i][j] = 0.f;
#pragma unroll
        for (int d = 0; d < HDIM; d++) {
            float a[4], kk[4];
#pragma unroll
            for (int i = 0; i < 4; i++) a[i]  = Qs[(tr + 16 * i) * AST + d];
#pragma unroll
            for (int j = 0; j < 4; j++) kk[j] = Ks[(tc + 16 * j) * AST + d];
#pragma unroll
            for (int i = 0; i < 4; i++)
#pragma unroll
                for (int j = 0; j < 4; j++)
                    sacc[i][j] = fmaf(a[i], kk[j], sacc[i][j]);
        }
#pragma unroll
        for (int i = 0; i < 4; i++)
#pragma unroll
            for (int j = 0; j < 4; j++)
                Ss[(tr + 16 * i) * AST + tc + 16 * j] = sacc[i][j];
        __syncthreads();

        // online softmax: 4 lanes per row, each owns 16 cols
        float sv[16];
        float mloc = -1e30f;
#pragma unroll
        for (int jj = 0; jj < 16; jj++) {
            const int j = (q << 4) + jj;
            float s = Ss[r * AST + j];
            if (mfl[j] != 0.f) s = -20000.f;
            sv[jj] = s;
            mloc = fmaxf(mloc, s);
        }
        mloc = fmaxf(mloc, __shfl_xor_sync(0xffffffffu, mloc, 1));
        mloc = fmaxf(mloc, __shfl_xor_sync(0xffffffffu, mloc, 2));
        const float mnew  = fmaxf(m_run, mloc);
        const float alpha = __expf(m_run - mnew);
        float ls = 0.f;
#pragma unroll
        for (int jj = 0; jj < 16; jj++) {
            const float p = __expf(sv[jj] - mnew);
            Ss[r * AST + (q << 4) + jj] = p;
            ls += p;
        }
        ls += __shfl_xor_sync(0xffffffffu, ls, 1);
        ls += __shfl_xor_sync(0xffffffffu, ls, 2);
        l_run = l_run * alpha + ls;
        m_run = mnew;
        if (q == 0) alph[r] = alpha;
        __syncthreads();

        // rescale O, then O += P @ V
        float ar[4];
#pragma unroll
        for (int i = 0; i < 4; i++) ar[i] = alph[tr + 16 * i];
#pragma unroll
        for (int i = 0; i < 4; i++)
#pragma unroll
            for (int j = 0; j < 4; j++) acc[i][j] *= ar[i];

#pragma unroll
        for (int jk = 0; jk < 64; jk++) {
            float p[4], v[4];
#pragma unroll
            for (int i = 0; i < 4; i++) p[i] = Ss[(tr + 16 * i) * AST + jk];
#pragma unroll
            for (int j = 0; j < 4; j++) v[j] = Vs[jk * AST + tc + 16 * j];
#pragma unroll
            for (int i = 0; i < 4; i++)
#pragma unroll
                for (int j = 0; j < 4; j++)
                    acc[i][j] = fmaf(p[i], v[j], acc[i][j]);
        }
    }

    __syncthreads();
    if (q == 0) alph[r] = 1.f / l_run;
    __syncthreads();

    // write to g_Att as [b*2048 + n][h*64 + c]
    float* Og = g_Att + (size_t)((b << 11) + (qt << 6)) * DIM + (h << 6);
#pragma unroll
    for (int i = 0; i < 4; i++) {
        const float li = alph[tr + 16 * i];
#pragma unroll
        for (int j = 0; j < 4; j++)
            Og[(size_t)(tr + 16 * i) * DIM + tc + 16 * j] = acc[i][j] * li;
    }
}

// ---------------------------------------------------------------------------
extern "C" void kernel_launch(void* const* d_in, const int* in_sizes, int n_in,
                              void* d_out, int out_size)
{
    const float* x          = (const float*)d_in[0];
    const unsigned char* mk = (const unsigned char*)d_in[1];
    const float* Wq = (const float*)d_in[2];
    const float* bq = (const float*)d_in[3];
    const float* Wk = (const float*)d_in[4];
    const float* bk = (const float*)d_in[5];
    const float* Wv = (const float*)d_in[6];
    const float* bv = (const float*)d_in[7];
    const float* Wo = (const float*)d_in[8];
    const float* bo = (const float*)d_in[9];
    float* out = (float*)d_out;

    cudaFuncSetAttribute(attn64, cudaFuncAttributeMaxDynamicSharedMemorySize,
                         ATTN_SMEM);

    dim3 gg(DIM / 128, MROWS / 128);   // (8, 32)
    gemm4096<<<gg, 256>>>(x, Wq, bq, nullptr, 0);
    gemm4096<<<gg, 256>>>(x, Wk, bk, nullptr, 1);
    gemm4096<<<gg, 256>>>(x, Wv, bv, nullptr, 2);
    attn64<<<dim3(SEQ / 64, HEADS, BATCH), 256, ATTN_SMEM>>>(mk);
    gemm4096<<<gg, 256>>>(x, Wo, bo, out, 3);
}

// round 4
// speedup vs baseline: 1.2051x; 1.2051x over previous
#include <cuda_runtime.h>
#include <cuda_bf16.h>
#include <cstdint>

// ---------------------------------------------------------------------------
// MultiheadSelfAttention: B=2, N=2048, D=1024, H=16, hd=64, fp32.
// R3: packed fp32 math via fma.rn.f32x2 (SASS FFMA2, 2x fp32 throughput) +
//     conflict-free LDS.64 operand feeds (transposed W / K smem tiles).
// ---------------------------------------------------------------------------

#define BATCH   2
#define SEQ     2048
#define DIM     1024
#define HEADS   16
#define HDIM    64
#define MROWS   (BATCH * SEQ)            // 4096

__device__ float g_Q[BATCH * HEADS * SEQ * HDIM];    // 16 MB
__device__ float g_K[BATCH * HEADS * SEQ * HDIM];    // 16 MB
__device__ float g_V[BATCH * HEADS * SEQ * HDIM];    // 16 MB
__device__ float g_Att[MROWS * DIM];                 // 16 MB

typedef unsigned long long u64;

// ---- packed f32x2 helpers --------------------------------------------------
__device__ __forceinline__ u64 f2_dup(float x) {
    u64 r; unsigned xi = __float_as_uint(x);
    asm("mov.b64 %0, {%1, %1};" : "=l"(r) : "r"(xi));
    return r;
}
__device__ __forceinline__ void f2_unpack(u64 v, float& lo, float& hi) {
    unsigned a, b;
    asm("mov.b64 {%0, %1}, %2;" : "=r"(a), "=r"(b) : "l"(v));
    lo = __uint_as_float(a); hi = __uint_as_float(b);
}
__device__ __forceinline__ void f2_fma(u64& d, u64 a, u64 b) {
    asm("fma.rn.f32x2 %0, %1, %2, %0;" : "+l"(d) : "l"(a), "l"(b));
}
__device__ __forceinline__ void f2_mul(u64& d, u64 a) {
    asm("mul.rn.f32x2 %0, %1, %0;" : "+l"(d) : "l"(a));
}
__device__ __forceinline__ u64 lds64(uint32_t a) {
    u64 r; asm volatile("ld.shared.b64 %0, [%1];" : "=l"(r) : "r"(a));
    return r;
}
__device__ __forceinline__ void sts64(uint32_t a, u64 v) {
    asm volatile("st.shared.b64 [%0], %1;" :: "r"(a), "l"(v));
}
__device__ __forceinline__ uint32_t smaddr(const void* p) {
    uint32_t r;
    asm("{ .reg .u64 t; cvta.to.shared.u64 t, %1; cvt.u32.u64 %0, t; }"
        : "=r"(r) : "l"(p));
    return r;
}

// ---------------------------------------------------------------------------
// GEMM: C[m][n] = sum_k X[m][k] * W[n][k] + bias[n]
// M=4096, N=1024, K=1024. Tile 128x128x16, 256 threads.
// Micro: 8 rows (tr+16i) x 8 cols as 4 packed pairs (2*tc + 32*jp + p).
// W is stored TRANSPOSED in smem (Wst[k][n], stride 130 == 2 mod 32:
// scatter-stores and b64 reads both verified conflict-free).
// mode 0/1/2: X = input x, write g_Q/g_K/g_V head-transposed [B,H,N,64].
// mode 3:     X = g_Att, write Cp row-major.
// ---------------------------------------------------------------------------
#define WST 130

__global__ __launch_bounds__(256, 2)
void gemm4096(const float* __restrict__ Xp,
              const float* __restrict__ W,
              const float* __restrict__ bias,
              float* __restrict__ Cp,
              int mode)
{
    __shared__ float Xs[128][17];
    __shared__ float Wst[16][WST];

    const float* X = (mode == 3) ? g_Att : Xp;

    const int tid  = threadIdx.x;
    const int m0   = blockIdx.y << 7;
    const int n0   = blockIdx.x << 7;
    const int tr   = tid >> 4;        // 0..15
    const int tc   = tid & 15;        // 0..15
    const int lrow = tid >> 2;        // 0..63
    const int lc   = (tid & 3) << 2;  // 0,4,8,12

    u64 acc[8][4];
#pragma unroll
    for (int i = 0; i < 8; i++)
#pragma unroll
        for (int jp = 0; jp < 4; jp++) acc[i][jp] = 0ull;

    const float* Xg = X + (size_t)(m0 + lrow) * DIM + lc;
    const float* Wg = W + (size_t)(n0 + lrow) * DIM + lc;

    const uint32_t ws_base = smaddr(&Wst[0][0]);
    const uint32_t ws_rd   = ws_base + (uint32_t)(2 * tc) * 4u;

    for (int k0 = 0; k0 < DIM; k0 += 16) {
        float4 x0 = *(const float4*)(Xg + k0);
        float4 x1 = *(const float4*)(Xg + (size_t)64 * DIM + k0);
        float4 w0 = *(const float4*)(Wg + k0);
        float4 w1 = *(const float4*)(Wg + (size_t)64 * DIM + k0);

        Xs[lrow][lc + 0] = x0.x; Xs[lrow][lc + 1] = x0.y;
        Xs[lrow][lc + 2] = x0.z; Xs[lrow][lc + 3] = x0.w;
        Xs[lrow + 64][lc + 0] = x1.x; Xs[lrow + 64][lc + 1] = x1.y;
        Xs[lrow + 64][lc + 2] = x1.z; Xs[lrow + 64][lc + 3] = x1.w;

        // transposed W store: Wst[k][n]  (banks (2(lc+c)+lrow) mod 32: distinct)
        Wst[lc + 0][lrow] = w0.x; Wst[lc + 1][lrow] = w0.y;
        Wst[lc + 2][lrow] = w0.z; Wst[lc + 3][lrow] = w0.w;
        Wst[lc + 0][lrow + 64] = w1.x; Wst[lc + 1][lrow + 64] = w1.y;
        Wst[lc + 2][lrow + 64] = w1.z; Wst[lc + 3][lrow + 64] = w1.w;
        __syncthreads();

#pragma unroll
        for (int k = 0; k < 16; k++) {
            u64 b[4];
#pragma unroll
            for (int jp = 0; jp < 4; jp++)
                b[jp] = lds64(ws_rd + (uint32_t)(k * WST + 32 * jp) * 4u);
#pragma unroll
            for (int i = 0; i < 8; i++) {
                const u64 ad = f2_dup(Xs[tr + 16 * i][k]);
#pragma unroll
                for (int jp = 0; jp < 4; jp++) f2_fma(acc[i][jp], ad, b[jp]);
            }
        }
        __syncthreads();
    }

    float2 bb[4];
#pragma unroll
    for (int jp = 0; jp < 4; jp++)
        bb[jp] = *(const float2*)&bias[n0 + 2 * tc + 32 * jp];

    if (mode == 3) {
#pragma unroll
        for (int i = 0; i < 8; i++) {
            const int m = m0 + tr + 16 * i;
#pragma unroll
            for (int jp = 0; jp < 4; jp++) {
                float lo, hi; f2_unpack(acc[i][jp], lo, hi);
                float2 o; o.x = lo + bb[jp].x; o.y = hi + bb[jp].y;
                *(float2*)&Cp[(size_t)m * DIM + n0 + 2 * tc + 32 * jp] = o;
            }
        }
    } else {
        float* O = (mode == 0) ? g_Q : (mode == 1) ? g_K : g_V;
        const int bidx = m0 >> 11;
#pragma unroll
        for (int i = 0; i < 8; i++) {
            const int m  = m0 + tr + 16 * i;
            const int nn = m & (SEQ - 1);
#pragma unroll
            for (int jp = 0; jp < 4; jp++) {
                const int n  = n0 + 2 * tc + 32 * jp;   // even
                const int h  = n >> 6;
                const int dh = n & 63;                  // even, pair stays in head
                float lo, hi; f2_unpack(acc[i][jp], lo, hi);
                float2 o; o.x = lo + bb[jp].x; o.y = hi + bb[jp].y;
                *(float2*)&O[(size_t)((bidx << 4) + h) * (SEQ * HDIM)
                             + (size_t)nn * HDIM + dh] = o;
            }
        }
    }
}

// ---------------------------------------------------------------------------
// Flash attention, one block = (b, h, qtile of 64), 256 threads.
// All three GEMM phases use fma.rn.f32x2 with conflict-free LDS.64 feeds:
//   Qs [q][d] stride 66, Kst [d][kpos] stride 66 (transposed on load),
//   Vs [kpos][d] stride 66, Ss [q][kpos] stride 66.
// Softmax identical to R2 (row-ownership, shfl reductions).
// ---------------------------------------------------------------------------
#define AST 66
#define ATTN_SMEM ((4 * 64 * AST + 128) * (int)sizeof(float))   // 68096 B

__global__ __launch_bounds__(256, 2)
void attn64(const unsigned char* __restrict__ mask)
{
    extern __shared__ float sm[];
    float* Qs   = sm;                 // 64*66  [q][d]
    float* Kst  = Qs  + 64 * AST;     // 64*66  [d][kpos]
    float* Vs   = Kst + 64 * AST;     // 64*66  [kpos][d]
    float* Ss   = Vs  + 64 * AST;     // 64*66  [q][kpos]
    float* alph = Ss  + 64 * AST;     // 64
    float* mfl  = alph + 64;          // 64

    const int b   = blockIdx.z;
    const int h   = blockIdx.y;
    const int qt  = blockIdx.x;
    const int tid = threadIdx.x;

    const size_t bh = (size_t)((b << 4) + h) * (SEQ * HDIM);
    const float* Qg = g_Q + bh + (size_t)(qt << 6) * HDIM;
    const float* Kg = g_K + bh;
    const float* Vg = g_V + bh;
    const unsigned char* mg = mask + b * SEQ;

    const int lrow = tid >> 2;          // 0..63
    const int lc16 = (tid & 3) << 4;    // 0,16,32,48 (Q/V loads)
    const int lc4  = (tid & 3) << 2;    // 0,4,8,12   (K transpose loads)
    const int tr   = tid >> 4;          // 0..15
    const int tc   = tid & 15;          // 0..15
    const int r    = tid >> 2;          // softmax row
    const int q    = tid & 3;           // softmax lane-in-row

    const uint32_t qs_b = smaddr(Qs);
    const uint32_t ks_b = smaddr(Kst);
    const uint32_t vs_b = smaddr(Vs);
    const uint32_t ss_b = smaddr(Ss);
    const uint32_t colw = (uint32_t)(2 * tc) * 4u;   // packed-pair byte offset

    // load Q tile (pre-scaled by 1/sqrt(64))
#pragma unroll
    for (int c = 0; c < 16; c += 4) {
        float4 v = *(const float4*)(Qg + lrow * HDIM + lc16 + c);
        Qs[lrow * AST + lc16 + c + 0] = v.x * 0.125f;
        Qs[lrow * AST + lc16 + c + 1] = v.y * 0.125f;
        Qs[lrow * AST + lc16 + c + 2] = v.z * 0.125f;
        Qs[lrow * AST + lc16 + c + 3] = v.w * 0.125f;
    }

    float m_run = -1e30f, l_run = 0.f;
    u64 acc[4][2];
#pragma unroll
    for (int i = 0; i < 4; i++) { acc[i][0] = 0ull; acc[i][1] = 0ull; }

    for (int kt = 0; kt < SEQ / 64; kt++) {
        __syncthreads();   // protect Kst/Vs/Ss reuse from previous iteration

        const float* Kt = Kg + (size_t)(kt << 6) * HDIM;
        const float* Vt = Vg + (size_t)(kt << 6) * HDIM;

        // K: load [kpos][d], store transposed Kst[d][kpos] (conflict-free)
#pragma unroll
        for (int c4 = 0; c4 < 4; c4++) {
            float4 kv = *(const float4*)(Kt + lrow * HDIM + lc4 + 16 * c4);
            Kst[(lc4 + 16 * c4 + 0) * AST + lrow] = kv.x;
            Kst[(lc4 + 16 * c4 + 1) * AST + lrow] = kv.y;
            Kst[(lc4 + 16 * c4 + 2) * AST + lrow] = kv.z;
            Kst[(lc4 + 16 * c4 + 3) * AST + lrow] = kv.w;
        }
        // V: row-major
#pragma unroll
        for (int c = 0; c < 16; c += 4) {
            float4 vv = *(const float4*)(Vt + lrow * HDIM + lc16 + c);
            Vs[lrow * AST + lc16 + c + 0] = vv.x;
            Vs[lrow * AST + lc16 + c + 1] = vv.y;
            Vs[lrow * AST + lc16 + c + 2] = vv.z;
            Vs[lrow * AST + lc16 + c + 3] = vv.w;
        }
        if (tid < 64) mfl[tid] = mg[(kt << 6) + tid] ? 1.f : 0.f;
        __syncthreads();

        // S = Qs @ Kst   (4 rows x 2 packed col-pairs per thread)
        u64 sacc[4][2];
#pragma unroll
        for (int i = 0; i < 4; i++) { sacc[i][0] = 0ull; sacc[i][1] = 0ull; }

#pragma unroll
        for (int d = 0; d < HDIM; d += 2) {
            float alo[4], ahi[4];
#pragma unroll
            for (int i = 0; i < 4; i++) {
                u64 a2 = lds64(qs_b + (uint32_t)((tr + 16 * i) * AST + d) * 4u);
                f2_unpack(a2, alo[i], ahi[i]);
            }
            u64 k0[2], k1[2];
#pragma unroll
            for (int jp = 0; jp < 2; jp++) {
                k0[jp] = lds64(ks_b + (uint32_t)(d * AST + 32 * jp) * 4u + colw);
                k1[jp] = lds64(ks_b + (uint32_t)((d + 1) * AST + 32 * jp) * 4u + colw);
            }
#pragma unroll
            for (int i = 0; i < 4; i++) {
                const u64 ad = f2_dup(alo[i]);
                f2_fma(sacc[i][0], ad, k0[0]);
                f2_fma(sacc[i][1], ad, k0[1]);
            }
#pragma unroll
            for (int i = 0; i < 4; i++) {
                const u64 ad = f2_dup(ahi[i]);
                f2_fma(sacc[i][0], ad, k1[0]);
                f2_fma(sacc[i][1], ad, k1[1]);
            }
        }
#pragma unroll
        for (int i = 0; i < 4; i++)
#pragma unroll
            for (int jp = 0; jp < 2; jp++)
                sts64(ss_b + (uint32_t)((tr + 16 * i) * AST + 32 * jp) * 4u + colw,
                      sacc[i][jp]);
        __syncthreads();

        // online softmax: 4 lanes per row, each owns 16 contiguous cols
        float sv[16];
        float mloc = -1e30f;
#pragma unroll
        for (int jj = 0; jj < 16; jj++) {
            const int j = (q << 4) + jj;
            float s = Ss[r * AST + j];
            if (mfl[j] != 0.f) s = -20000.f;
            sv[jj] = s;
            mloc = fmaxf(mloc, s);
        }
        mloc = fmaxf(mloc, __shfl_xor_sync(0xffffffffu, mloc, 1));
        mloc = fmaxf(mloc, __shfl_xor_sync(0xffffffffu, mloc, 2));
        const float mnew  = fmaxf(m_run, mloc);
        const float alpha = __expf(m_run - mnew);
        float ls = 0.f;
#pragma unroll
        for (int jj = 0; jj < 16; jj++) {
            const float p = __expf(sv[jj] - mnew);
            Ss[r * AST + (q << 4) + jj] = p;
            ls += p;
        }
        ls += __shfl_xor_sync(0xffffffffu, ls, 1);
        ls += __shfl_xor_sync(0xffffffffu, ls, 2);
        l_run = l_run * alpha + ls;
        m_run = mnew;
        if (q == 0) alph[r] = alpha;
        __syncthreads();

        // rescale O, then O += P @ V
#pragma unroll
        for (int i = 0; i < 4; i++) {
            const u64 ad = f2_dup(alph[tr + 16 * i]);
            f2_mul(acc[i][0], ad);
            f2_mul(acc[i][1], ad);
        }

#pragma unroll
        for (int jk = 0; jk < 64; jk += 2) {
            float plo[4], phi[4];
#pragma unroll
            for (int i = 0; i < 4; i++) {
                u64 p2 = lds64(ss_b + (uint32_t)((tr + 16 * i) * AST + jk) * 4u);
                f2_unpack(p2, plo[i], phi[i]);
            }
            u64 v0[2], v1[2];
#pragma unroll
            for (int jp = 0; jp < 2; jp++) {
                v0[jp] = lds64(vs_b + (uint32_t)(jk * AST + 32 * jp) * 4u + colw);
                v1[jp] = lds64(vs_b + (uint32_t)((jk + 1) * AST + 32 * jp) * 4u + colw);
            }
#pragma unroll
            for (int i = 0; i < 4; i++) {
                const u64 pd = f2_dup(plo[i]);
                f2_fma(acc[i][0], pd, v0[0]);
                f2_fma(acc[i][1], pd, v0[1]);
            }
#pragma unroll
            for (int i = 0; i < 4; i++) {
                const u64 pd = f2_dup(phi[i]);
                f2_fma(acc[i][0], pd, v1[0]);
                f2_fma(acc[i][1], pd, v1[1]);
            }
        }
    }

    __syncthreads();
    if (q == 0) alph[r] = 1.f / l_run;
    __syncthreads();

    // write to g_Att as [b*2048 + n][h*64 + c]
    float* Og = g_Att + (size_t)((b << 11) + (qt << 6)) * DIM + (h << 6);
#pragma unroll
    for (int i = 0; i < 4; i++) {
        const u64 ld = f2_dup(alph[tr + 16 * i]);
#pragma unroll
        for (int jp = 0; jp < 2; jp++) {
            u64 o = acc[i][jp];
            f2_mul(o, ld);
            float lo, hi; f2_unpack(o, lo, hi);
            float2 ov; ov.x = lo; ov.y = hi;
            *(float2*)&Og[(size_t)(tr + 16 * i) * DIM + 2 * tc + 32 * jp] = ov;
        }
    }
}

// ---------------------------------------------------------------------------
extern "C" void kernel_launch(void* const* d_in, const int* in_sizes, int n_in,
                              void* d_out, int out_size)
{
    const float* x          = (const float*)d_in[0];
    const unsigned char* mk = (const unsigned char*)d_in[1];
    const float* Wq = (const float*)d_in[2];
    const float* bq = (const float*)d_in[3];
    const float* Wk = (const float*)d_in[4];
    const float* bk = (const float*)d_in[5];
    const float* Wv = (const float*)d_in[6];
    const float* bv = (const float*)d_in[7];
    const float* Wo = (const float*)d_in[8];
    const float* bo = (const float*)d_in[9];
    float* out = (float*)d_out;

    cudaFuncSetAttribute(attn64, cudaFuncAttributeMaxDynamicSharedMemorySize,
                         ATTN_SMEM);

    dim3 gg(DIM / 128, MROWS / 128);   // (8, 32)
    gemm4096<<<gg, 256>>>(x, Wq, bq, nullptr, 0);
    gemm4096<<<gg, 256>>>(x, Wk, bk, nullptr, 1);
    gemm4096<<<gg, 256>>>(x, Wv, bv, nullptr, 2);
    attn64<<<dim3(SEQ / 64, HEADS, BATCH), 256, ATTN_SMEM>>>(mk);
    gemm4096<<<gg, 256>>>(x, Wo, bo, out, 3);
}

// round 9
// speedup vs baseline: 1.6160x; 1.3410x over previous
#include <cuda_runtime.h>
#include <cuda_bf16.h>
#include <cstdint>

// ---------------------------------------------------------------------------
// MultiheadSelfAttention: B=2, N=2048, D=1024, H=16, hd=64, fp32.
// R7: identical to R6 (bench infra failed; resubmitting unchanged).
// tcgen05 is sm_103a-gated and this harness compiles for compute_103 ->
// use mma.sync.m16n8k16 bf16 (HMMA) + ldmatrix, with the bf16 hi/lo split
// for accuracy. Flash attention stays SIMT f32x2 (R3).
// ---------------------------------------------------------------------------

#define BATCH   2
#define SEQ     2048
#define DIM     1024
#define HEADS   16
#define HDIM    64
#define MROWS   (BATCH * SEQ)            // 4096

__device__ float g_Q[BATCH * HEADS * SEQ * HDIM];
__device__ float g_K[BATCH * HEADS * SEQ * HDIM];
__device__ float g_V[BATCH * HEADS * SEQ * HDIM];
__device__ float g_Att[MROWS * DIM];

// bf16 hi/lo split scratch
__device__ __nv_bfloat16 g_xh[MROWS * DIM], g_xl[MROWS * DIM];
__device__ __nv_bfloat16 g_wh[4][DIM * DIM], g_wl[4][DIM * DIM];
__device__ __nv_bfloat16 g_ah[MROWS * DIM], g_al[MROWS * DIM];

typedef unsigned long long u64;

// ---- generic helpers -------------------------------------------------------
__device__ __forceinline__ uint32_t smaddr(const void* p) {
    uint32_t r;
    asm("{ .reg .u64 t; cvta.to.shared.u64 t, %1; cvt.u32.u64 %0, t; }"
        : "=r"(r) : "l"(p));
    return r;
}
__device__ __forceinline__ void cpa16(uint32_t dst, const void* src) {
    asm volatile("cp.async.cg.shared.global [%0], [%1], 16;"
                 :: "r"(dst), "l"(src) : "memory");
}
__device__ __forceinline__ void ldsm4(uint32_t* r, uint32_t addr) {
    asm volatile("ldmatrix.sync.aligned.m8n8.x4.shared.b16 {%0,%1,%2,%3}, [%4];"
                 : "=r"(r[0]), "=r"(r[1]), "=r"(r[2]), "=r"(r[3]) : "r"(addr));
}
__device__ __forceinline__ void mma_bf16(float* d, const uint32_t* a,
                                         uint32_t b0, uint32_t b1) {
    asm volatile(
        "mma.sync.aligned.m16n8k16.row.col.f32.bf16.bf16.f32 "
        "{%0,%1,%2,%3}, {%4,%5,%6,%7}, {%8,%9}, {%0,%1,%2,%3};"
        : "+f"(d[0]), "+f"(d[1]), "+f"(d[2]), "+f"(d[3])
        : "r"(a[0]), "r"(a[1]), "r"(a[2]), "r"(a[3]), "r"(b0), "r"(b1));
}

// ---- f32x2 helpers (attn kernel) ------------------------------------------
__device__ __forceinline__ u64 f2_dup(float x) {
    u64 r; unsigned xi = __float_as_uint(x);
    asm("mov.b64 %0, {%1, %1};" : "=l"(r) : "r"(xi));
    return r;
}
__device__ __forceinline__ void f2_unpack(u64 v, float& lo, float& hi) {
    unsigned a, b;
    asm("mov.b64 {%0, %1}, %2;" : "=r"(a), "=r"(b) : "l"(v));
    lo = __uint_as_float(a); hi = __uint_as_float(b);
}
__device__ __forceinline__ void f2_fma(u64& d, u64 a, u64 b) {
    asm("fma.rn.f32x2 %0, %1, %2, %0;" : "+l"(d) : "l"(a), "l"(b));
}
__device__ __forceinline__ void f2_mul(u64& d, u64 a) {
    asm("mul.rn.f32x2 %0, %1, %0;" : "+l"(d) : "l"(a));
}
__device__ __forceinline__ u64 lds64(uint32_t a) {
    u64 r; asm volatile("ld.shared.b64 %0, [%1];" : "=l"(r) : "r"(a));
    return r;
}
__device__ __forceinline__ void sts64(uint32_t a, u64 v) {
    asm volatile("st.shared.b64 [%0], %1;" :: "r"(a), "l"(v));
}

// ---------------------------------------------------------------------------
// bf16 hi/lo split pre-pass.  which: 0=x, 1..4=Wq/Wk/Wv/Wo, 5=g_Att
// ---------------------------------------------------------------------------
__global__ void split_bf16(const float* __restrict__ xsrc, int which)
{
    const float* s;
    __nv_bfloat16 *h, *l;
    switch (which) {
        case 0:  s = xsrc;  h = g_xh;    l = g_xl;    break;
        case 1:  s = xsrc;  h = g_wh[0]; l = g_wl[0]; break;
        case 2:  s = xsrc;  h = g_wh[1]; l = g_wl[1]; break;
        case 3:  s = xsrc;  h = g_wh[2]; l = g_wl[2]; break;
        case 4:  s = xsrc;  h = g_wh[3]; l = g_wl[3]; break;
        default: s = g_Att; h = g_ah;    l = g_al;    break;
    }
    const int i = (blockIdx.x * blockDim.x + threadIdx.x) << 2;
    float4 v = *(const float4*)(s + i);
    __nv_bfloat16 h0 = __float2bfloat16(v.x);
    __nv_bfloat16 h1 = __float2bfloat16(v.y);
    __nv_bfloat16 h2 = __float2bfloat16(v.z);
    __nv_bfloat16 h3 = __float2bfloat16(v.w);
    __nv_bfloat16 l0 = __float2bfloat16(v.x - __bfloat162float(h0));
    __nv_bfloat16 l1 = __float2bfloat16(v.y - __bfloat162float(h1));
    __nv_bfloat16 l2 = __float2bfloat16(v.z - __bfloat162float(h2));
    __nv_bfloat16 l3 = __float2bfloat16(v.w - __bfloat162float(h3));
    __nv_bfloat162 ph0; ph0.x = h0; ph0.y = h1;
    __nv_bfloat162 ph1; ph1.x = h2; ph1.y = h3;
    __nv_bfloat162 pl0; pl0.x = l0; pl0.y = l1;
    __nv_bfloat162 pl1; pl1.x = l2; pl1.y = l3;
    *(__nv_bfloat162*)(h + i)     = ph0;
    *(__nv_bfloat162*)(h + i + 2) = ph1;
    *(__nv_bfloat162*)(l + i)     = pl0;
    *(__nv_bfloat162*)(l + i + 2) = pl1;
}

// ---------------------------------------------------------------------------
// HMMA GEMM:  C[m][n] = sum_k A[m][k]*B[n][k] + bias[n]
// bf16 hi/lo split: C = AhBh + AhBl + AlBh.
// CTA tile 128x128, 256 threads (warps 4m x 2n, warp tile 32x64), K-chunk 64,
// double-buffered cp.async smem, row stride 144 B (conflict-free ldmatrix).
// mode 0/1/2: A=x-split, B=W[mode], write g_Q/g_K/g_V head-transposed.
// mode 3:     A=att-split, B=W[3], write Cp row-major.
// ---------------------------------------------------------------------------
#define OPB   18432                       // 128 rows * 144 B
#define STG   (4 * OPB)                   // Ah, Al, Bh, Bl = 73728
#define GEMM_SMEM (2 * STG)               // 147456

__global__ __launch_bounds__(256, 1)
void gemm_hmma(const float* __restrict__ bias, float* __restrict__ Cp, int mode)
{
    extern __shared__ char smraw[];
    const uint32_t sb = smaddr(smraw);

    const int tid  = threadIdx.x;
    const int wid  = tid >> 5;
    const int lane = tid & 31;
    const int n0   = blockIdx.x << 7;
    const int m0   = blockIdx.y << 7;

    const int widx = (mode == 3) ? 3 : mode;
    const __nv_bfloat16* Ah = (mode == 3) ? g_ah : g_xh;
    const __nv_bfloat16* Al = (mode == 3) ? g_al : g_xl;
    const __nv_bfloat16* Bh = g_wh[widx];
    const __nv_bfloat16* Bl = g_wl[widx];

    float acc[2][8][4];
#pragma unroll
    for (int mi = 0; mi < 2; mi++)
#pragma unroll
        for (int nj = 0; nj < 8; nj++)
#pragma unroll
            for (int e = 0; e < 4; e++) acc[mi][nj][e] = 0.f;

    const int lr = tid >> 3;      // 0..31
    const int lu = tid & 7;       // 16B unit in 128B of data

    // fragment addressing
    const int wm  = wid & 3;          // m quadrant (32 rows)
    const int wn  = wid >> 2;         // n half (64 cols)
    const int rl  = lane & 7;
    const int seg = lane >> 3;
    const uint32_t a_off =
        (uint32_t)((wm * 32 + rl + (seg & 1) * 8) * 144 + ((seg >> 1) * 8) * 2);
    const uint32_t b_off =
        (uint32_t)((wn * 64 + rl + (seg & 1) * 8) * 144 + ((seg >> 1) * 8) * 2);

    // ---- prologue: load stage 0 ----
    {
        const uint32_t stg = sb;
#pragma unroll
        for (int i = 0; i < 4; i++) {
            const int r = lr + 32 * i;
            const uint32_t dofs = (uint32_t)(r * 144 + lu * 16);
            cpa16(stg + 0 * OPB + dofs, Ah + (size_t)(m0 + r) * DIM + lu * 8);
            cpa16(stg + 1 * OPB + dofs, Al + (size_t)(m0 + r) * DIM + lu * 8);
            cpa16(stg + 2 * OPB + dofs, Bh + (size_t)(n0 + r) * DIM + lu * 8);
            cpa16(stg + 3 * OPB + dofs, Bl + (size_t)(n0 + r) * DIM + lu * 8);
        }
        asm volatile("cp.async.commit_group;" ::: "memory");
    }

    for (int c = 0; c < 16; c++) {
        if (c + 1 < 16) {
            const uint32_t stg = sb + (uint32_t)((c + 1) & 1) * STG;
            const int k0 = (c + 1) << 6;
#pragma unroll
            for (int i = 0; i < 4; i++) {
                const int r = lr + 32 * i;
                const uint32_t dofs = (uint32_t)(r * 144 + lu * 16);
                cpa16(stg + 0 * OPB + dofs, Ah + (size_t)(m0 + r) * DIM + k0 + lu * 8);
                cpa16(stg + 1 * OPB + dofs, Al + (size_t)(m0 + r) * DIM + k0 + lu * 8);
                cpa16(stg + 2 * OPB + dofs, Bh + (size_t)(n0 + r) * DIM + k0 + lu * 8);
                cpa16(stg + 3 * OPB + dofs, Bl + (size_t)(n0 + r) * DIM + k0 + lu * 8);
            }
            asm volatile("cp.async.commit_group;" ::: "memory");
            asm volatile("cp.async.wait_group 1;" ::: "memory");
        } else {
            asm volatile("cp.async.wait_group 0;" ::: "memory");
        }
        __syncthreads();

        const uint32_t stg = sb + (uint32_t)(c & 1) * STG;
#pragma unroll
        for (int ks = 0; ks < 4; ks++) {
            uint32_t fah[2][4], fal[2][4];
#pragma unroll
            for (int mi = 0; mi < 2; mi++) {
                ldsm4(fah[mi], stg + 0 * OPB + a_off + mi * 2304 + ks * 32);
                ldsm4(fal[mi], stg + 1 * OPB + a_off + mi * 2304 + ks * 32);
            }
            uint32_t fbh[4][4], fbl[4][4];
#pragma unroll
            for (int bj = 0; bj < 4; bj++) {
                ldsm4(fbh[bj], stg + 2 * OPB + b_off + bj * 2304 + ks * 32);
                ldsm4(fbl[bj], stg + 3 * OPB + b_off + bj * 2304 + ks * 32);
            }
#pragma unroll
            for (int mi = 0; mi < 2; mi++)
#pragma unroll
                for (int bj = 0; bj < 4; bj++) {
                    mma_bf16(acc[mi][2 * bj + 0], fah[mi], fbh[bj][0], fbh[bj][2]);
                    mma_bf16(acc[mi][2 * bj + 1], fah[mi], fbh[bj][1], fbh[bj][3]);
                    mma_bf16(acc[mi][2 * bj + 0], fah[mi], fbl[bj][0], fbl[bj][2]);
                    mma_bf16(acc[mi][2 * bj + 1], fah[mi], fbl[bj][1], fbl[bj][3]);
                    mma_bf16(acc[mi][2 * bj + 0], fal[mi], fbh[bj][0], fbh[bj][2]);
                    mma_bf16(acc[mi][2 * bj + 1], fal[mi], fbh[bj][1], fbh[bj][3]);
                }
        }
        __syncthreads();
    }

    // ---- epilogue ----
    const int qrow = lane >> 2;          // 0..7
    const int qcol = (lane & 3) << 1;    // 0,2,4,6
#pragma unroll
    for (int mi = 0; mi < 2; mi++) {
#pragma unroll
        for (int nj = 0; nj < 8; nj++) {
            const int col = n0 + wn * 64 + nj * 8 + qcol;
            const float2 bv = *(const float2*)&bias[col];
            const int mrow = m0 + wm * 32 + mi * 16 + qrow;
#pragma unroll
            for (int half = 0; half < 2; half++) {
                const int m = mrow + half * 8;
                float2 o;
                o.x = acc[mi][nj][2 * half + 0] + bv.x;
                o.y = acc[mi][nj][2 * half + 1] + bv.y;
                if (mode == 3) {
                    *(float2*)&Cp[(size_t)m * DIM + col] = o;
                } else {
                    float* G = (mode == 0) ? g_Q : (mode == 1) ? g_K : g_V;
                    const int h    = col >> 6;
                    const int dh   = col & 63;       // even: pair in one head
                    const int bidx = m >> 11;
                    const int nn   = m & (SEQ - 1);
                    *(float2*)&G[(size_t)((bidx << 4) + h) * (SEQ * HDIM)
                                 + (size_t)nn * HDIM + dh] = o;
                }
            }
        }
    }
}

// ---------------------------------------------------------------------------
// Flash attention (R3, unchanged): f32x2 SIMT, one block = (b, h, 64-q-tile).
// ---------------------------------------------------------------------------
#define AST 66
#define ATTN_SMEM ((4 * 64 * AST + 128) * (int)sizeof(float))   // 68096 B

__global__ __launch_bounds__(256, 2)
void attn64(const unsigned char* __restrict__ mask)
{
    extern __shared__ float sm[];
    float* Qs   = sm;
    float* Kst  = Qs  + 64 * AST;
    float* Vs   = Kst + 64 * AST;
    float* Ss   = Vs  + 64 * AST;
    float* alph = Ss  + 64 * AST;
    float* mfl  = alph + 64;

    const int b   = blockIdx.z;
    const int h   = blockIdx.y;
    const int qt  = blockIdx.x;
    const int tid = threadIdx.x;

    const size_t bh = (size_t)((b << 4) + h) * (SEQ * HDIM);
    const float* Qg = g_Q + bh + (size_t)(qt << 6) * HDIM;
    const float* Kg = g_K + bh;
    const float* Vg = g_V + bh;
    const unsigned char* mg = mask + b * SEQ;

    const int lrow = tid >> 2;
    const int lc16 = (tid & 3) << 4;
    const int lc4  = (tid & 3) << 2;
    const int tr   = tid >> 4;
    const int tc   = tid & 15;
    const int r    = tid >> 2;
    const int q    = tid & 3;

    const uint32_t qs_b = smaddr(Qs);
    const uint32_t ks_b = smaddr(Kst);
    const uint32_t vs_b = smaddr(Vs);
    const uint32_t ss_b = smaddr(Ss);
    const uint32_t colw = (uint32_t)(2 * tc) * 4u;

#pragma unroll
    for (int c = 0; c < 16; c += 4) {
        float4 v = *(const float4*)(Qg + lrow * HDIM + lc16 + c);
        Qs[lrow * AST + lc16 + c + 0] = v.x * 0.125f;
        Qs[lrow * AST + lc16 + c + 1] = v.y * 0.125f;
        Qs[lrow * AST + lc16 + c + 2] = v.z * 0.125f;
        Qs[lrow * AST + lc16 + c + 3] = v.w * 0.125f;
    }

    float m_run = -1e30f, l_run = 0.f;
    u64 acc[4][2];
#pragma unroll
    for (int i = 0; i < 4; i++) { acc[i][0] = 0ull; acc[i][1] = 0ull; }

    for (int kt = 0; kt < SEQ / 64; kt++) {
        __syncthreads();

        const float* Kt = Kg + (size_t)(kt << 6) * HDIM;
        const float* Vt = Vg + (size_t)(kt << 6) * HDIM;

#pragma unroll
        for (int c4 = 0; c4 < 4; c4++) {
            float4 kv = *(const float4*)(Kt + lrow * HDIM + lc4 + 16 * c4);
            Kst[(lc4 + 16 * c4 + 0) * AST + lrow] = kv.x;
            Kst[(lc4 + 16 * c4 + 1) * AST + lrow] = kv.y;
            Kst[(lc4 + 16 * c4 + 2) * AST + lrow] = kv.z;
            Kst[(lc4 + 16 * c4 + 3) * AST + lrow] = kv.w;
        }
#pragma unroll
        for (int c = 0; c < 16; c += 4) {
            float4 vv = *(const float4*)(Vt + lrow * HDIM + lc16 + c);
            Vs[lrow * AST + lc16 + c + 0] = vv.x;
            Vs[lrow * AST + lc16 + c + 1] = vv.y;
            Vs[lrow * AST + lc16 + c + 2] = vv.z;
            Vs[lrow * AST + lc16 + c + 3] = vv.w;
        }
        if (tid < 64) mfl[tid] = mg[(kt << 6) + tid] ? 1.f : 0.f;
        __syncthreads();

        u64 sacc[4][2];
#pragma unroll
        for (int i = 0; i < 4; i++) { sacc[i][0] = 0ull; sacc[i][1] = 0ull; }

#pragma unroll
        for (int d = 0; d < HDIM; d += 2) {
            float alo[4], ahi[4];
#pragma unroll
            for (int i = 0; i < 4; i++) {
                u64 a2 = lds64(qs_b + (uint32_t)((tr + 16 * i) * AST + d) * 4u);
                f2_unpack(a2, alo[i], ahi[i]);
            }
            u64 k0[2], k1[2];
#pragma unroll
            for (int jp = 0; jp < 2; jp++) {
                k0[jp] = lds64(ks_b + (uint32_t)(d * AST + 32 * jp) * 4u + colw);
                k1[jp] = lds64(ks_b + (uint32_t)((d + 1) * AST + 32 * jp) * 4u + colw);
            }
#pragma unroll
            for (int i = 0; i < 4; i++) {
                const u64 ad = f2_dup(alo[i]);
                f2_fma(sacc[i][0], ad, k0[0]);
                f2_fma(sacc[i][1], ad, k0[1]);
            }
#pragma unroll
            for (int i = 0; i < 4; i++) {
                const u64 ad = f2_dup(ahi[i]);
                f2_fma(sacc[i][0], ad, k1[0]);
                f2_fma(sacc[i][1], ad, k1[1]);
            }
        }
#pragma unroll
        for (int i = 0; i < 4; i++)
#pragma unroll
            for (int jp = 0; jp < 2; jp++)
                sts64(ss_b + (uint32_t)((tr + 16 * i) * AST + 32 * jp) * 4u + colw,
                      sacc[i][jp]);
        __syncthreads();

        float sv[16];
        float mloc = -1e30f;
#pragma unroll
        for (int jj = 0; jj < 16; jj++) {
            const int j = (q << 4) + jj;
            float s = Ss[r * AST + j];
            if (mfl[j] != 0.f) s = -20000.f;
            sv[jj] = s;
            mloc = fmaxf(mloc, s);
        }
        mloc = fmaxf(mloc, __shfl_xor_sync(0xffffffffu, mloc, 1));
        mloc = fmaxf(mloc, __shfl_xor_sync(0xffffffffu, mloc, 2));
        const float mnew  = fmaxf(m_run, mloc);
        const float alpha = __expf(m_run - mnew);
        float ls = 0.f;
#pragma unroll
        for (int jj = 0; jj < 16; jj++) {
            const float p = __expf(sv[jj] - mnew);
            Ss[r * AST + (q << 4) + jj] = p;
            ls += p;
        }
        ls += __shfl_xor_sync(0xffffffffu, ls, 1);
        ls += __shfl_xor_sync(0xffffffffu, ls, 2);
        l_run = l_run * alpha + ls;
        m_run = mnew;
        if (q == 0) alph[r] = alpha;
        __syncthreads();

#pragma unroll
        for (int i = 0; i < 4; i++) {
            const u64 ad = f2_dup(alph[tr + 16 * i]);
            f2_mul(acc[i][0], ad);
            f2_mul(acc[i][1], ad);
        }

#pragma unroll
        for (int jk = 0; jk < 64; jk += 2) {
            float plo[4], phi[4];
#pragma unroll
            for (int i = 0; i < 4; i++) {
                u64 p2 = lds64(ss_b + (uint32_t)((tr + 16 * i) * AST + jk) * 4u);
                f2_unpack(p2, plo[i], phi[i]);
            }
            u64 v0[2], v1[2];
#pragma unroll
            for (int jp = 0; jp < 2; jp++) {
                v0[jp] = lds64(vs_b + (uint32_t)(jk * AST + 32 * jp) * 4u + colw);
                v1[jp] = lds64(vs_b + (uint32_t)((jk + 1) * AST + 32 * jp) * 4u + colw);
            }
#pragma unroll
            for (int i = 0; i < 4; i++) {
                const u64 pd = f2_dup(plo[i]);
                f2_fma(acc[i][0], pd, v0[0]);
                f2_fma(acc[i][1], pd, v0[1]);
            }
#pragma unroll
            for (int i = 0; i < 4; i++) {
                const u64 pd = f2_dup(phi[i]);
                f2_fma(acc[i][0], pd, v1[0]);
                f2_fma(acc[i][1], pd, v1[1]);
            }
        }
    }

    __syncthreads();
    if (q == 0) alph[r] = 1.f / l_run;
    __syncthreads();

    float* Og = g_Att + (size_t)((b << 11) + (qt << 6)) * DIM + (h << 6);
#pragma unroll
    for (int i = 0; i < 4; i++) {
        const u64 ld = f2_dup(alph[tr + 16 * i]);
#pragma unroll
        for (int jp = 0; jp < 2; jp++) {
            u64 o = acc[i][jp];
            f2_mul(o, ld);
            float lo, hi; f2_unpack(o, lo, hi);
            float2 ov; ov.x = lo; ov.y = hi;
            *(float2*)&Og[(size_t)(tr + 16 * i) * DIM + 2 * tc + 32 * jp] = ov;
        }
    }
}

// ---------------------------------------------------------------------------
extern "C" void kernel_launch(void* const* d_in, const int* in_sizes, int n_in,
                              void* d_out, int out_size)
{
    const float* x          = (const float*)d_in[0];
    const unsigned char* mk = (const unsigned char*)d_in[1];
    const float* Wq = (const float*)d_in[2];
    const float* bq = (const float*)d_in[3];
    const float* Wk = (const float*)d_in[4];
    const float* bk = (const float*)d_in[5];
    const float* Wv = (const float*)d_in[6];
    const float* bv = (const float*)d_in[7];
    const float* Wo = (const float*)d_in[8];
    const float* bo = (const float*)d_in[9];
    float* out = (float*)d_out;

    cudaFuncSetAttribute(gemm_hmma, cudaFuncAttributeMaxDynamicSharedMemorySize,
                         GEMM_SMEM);
    cudaFuncSetAttribute(attn64, cudaFuncAttributeMaxDynamicSharedMemorySize,
                         ATTN_SMEM);

    // bf16 hi/lo splits
    split_bf16<<<MROWS * DIM / 1024, 256>>>(x,  0);
    split_bf16<<<DIM * DIM / 1024,  256>>>(Wq, 1);
    split_bf16<<<DIM * DIM / 1024,  256>>>(Wk, 2);
    split_bf16<<<DIM * DIM / 1024,  256>>>(Wv, 3);
    split_bf16<<<DIM * DIM / 1024,  256>>>(Wv, 3);
    split_bf16<<<DIM * DIM / 1024,  256>>>(Wo, 4);

    dim3 gg(DIM / 128, MROWS / 128);   // (8, 32)
    gemm_hmma<<<gg, 256, GEMM_SMEM>>>(bq, out, 0);
    gemm_hmma<<<gg, 256, GEMM_SMEM>>>(bk, out, 1);
    gemm_hmma<<<gg, 256, GEMM_SMEM>>>(bv, out, 2);

    attn64<<<dim3(SEQ / 64, HEADS, BATCH), 256, ATTN_SMEM>>>(mk);

    split_bf16<<<MROWS * DIM / 1024, 256>>>(nullptr, 5);
    gemm_hmma<<<gg, 256, GEMM_SMEM>>>(bo, out, 3);
}

// round 10
// speedup vs baseline: 3.0858x; 1.9095x over previous
#include <cuda_runtime.h>
#include <cuda_bf16.h>
#include <cstdint>

// ---------------------------------------------------------------------------
// MultiheadSelfAttention: B=2, N=2048, D=1024, H=16, hd=64, fp32.
// R10: HMMA everywhere. GEMMs as in R6 (bf16 hi/lo split). Attention now
// also on mma.sync bf16 with hi/lo split for S=QK^T and O=PV; online softmax
// in registers. Q/K/V flow gemm->attn as bf16 hi/lo directly.
// ---------------------------------------------------------------------------

#define BATCH   2
#define SEQ     2048
#define DIM     1024
#define HEADS   16
#define HDIM    64
#define MROWS   (BATCH * SEQ)            // 4096

__device__ float g_Att[MROWS * DIM];

// bf16 hi/lo split scratch
__device__ __nv_bfloat16 g_xh[MROWS * DIM], g_xl[MROWS * DIM];
__device__ __nv_bfloat16 g_wh[4][DIM * DIM], g_wl[4][DIM * DIM];
__device__ __nv_bfloat16 g_ah[MROWS * DIM], g_al[MROWS * DIM];
// Q/K/V as bf16 hi/lo, head-transposed [B*H][SEQ][64]
#define QKVN (BATCH * HEADS * SEQ * HDIM)
__device__ __nv_bfloat16 g_Qh[QKVN], g_Ql[QKVN];
__device__ __nv_bfloat16 g_Kh[QKVN], g_Kl[QKVN];
__device__ __nv_bfloat16 g_Vh[QKVN], g_Vl[QKVN];

typedef unsigned long long u64;

// ---- helpers ---------------------------------------------------------------
__device__ __forceinline__ uint32_t smaddr(const void* p) {
    uint32_t r;
    asm("{ .reg .u64 t; cvta.to.shared.u64 t, %1; cvt.u32.u64 %0, t; }"
        : "=r"(r) : "l"(p));
    return r;
}
__device__ __forceinline__ void cpa16(uint32_t dst, const void* src) {
    asm volatile("cp.async.cg.shared.global [%0], [%1], 16;"
                 :: "r"(dst), "l"(src) : "memory");
}
__device__ __forceinline__ void ldsm4(uint32_t* r, uint32_t addr) {
    asm volatile("ldmatrix.sync.aligned.m8n8.x4.shared.b16 {%0,%1,%2,%3}, [%4];"
                 : "=r"(r[0]), "=r"(r[1]), "=r"(r[2]), "=r"(r[3]) : "r"(addr));
}
__device__ __forceinline__ void ldsm4t(uint32_t* r, uint32_t addr) {
    asm volatile("ldmatrix.sync.aligned.m8n8.x4.trans.shared.b16 {%0,%1,%2,%3}, [%4];"
                 : "=r"(r[0]), "=r"(r[1]), "=r"(r[2]), "=r"(r[3]) : "r"(addr));
}
__device__ __forceinline__ void mma_bf16(float* d, const uint32_t* a,
                                         uint32_t b0, uint32_t b1) {
    asm volatile(
        "mma.sync.aligned.m16n8k16.row.col.f32.bf16.bf16.f32 "
        "{%0,%1,%2,%3}, {%4,%5,%6,%7}, {%8,%9}, {%0,%1,%2,%3};"
        : "+f"(d[0]), "+f"(d[1]), "+f"(d[2]), "+f"(d[3])
        : "r"(a[0]), "r"(a[1]), "r"(a[2]), "r"(a[3]), "r"(b0), "r"(b1));
}
// pack two f32 -> bf16x2 (lo = x, hi = y)
__device__ __forceinline__ uint32_t packbf(float x, float y) {
    uint32_t r;
    asm("cvt.rn.bf16x2.f32 %0, %1, %2;" : "=r"(r) : "f"(y), "f"(x));
    return r;
}
__device__ __forceinline__ uint32_t ldsu16(uint32_t a) {
    uint32_t r;
    asm volatile("ld.shared.u16 %0, [%1];" : "=r"(r) : "r"(a));
    return r;
}

// ---------------------------------------------------------------------------
// bf16 hi/lo split pre-pass.  which: 0=x, 1..4=Wq/Wk/Wv/Wo, 5=g_Att
// ---------------------------------------------------------------------------
__global__ void split_bf16(const float* __restrict__ xsrc, int which)
{
    const float* s;
    __nv_bfloat16 *h, *l;
    switch (which) {
        case 0:  s = xsrc;  h = g_xh;    l = g_xl;    break;
        case 1:  s = xsrc;  h = g_wh[0]; l = g_wl[0]; break;
        case 2:  s = xsrc;  h = g_wh[1]; l = g_wl[1]; break;
        case 3:  s = xsrc;  h = g_wh[2]; l = g_wl[2]; break;
        case 4:  s = xsrc;  h = g_wh[3]; l = g_wl[3]; break;
        default: s = g_Att; h = g_ah;    l = g_al;    break;
    }
    const int i = (blockIdx.x * blockDim.x + threadIdx.x) << 2;
    float4 v = *(const float4*)(s + i);
    __nv_bfloat16 h0 = __float2bfloat16(v.x);
    __nv_bfloat16 h1 = __float2bfloat16(v.y);
    __nv_bfloat16 h2 = __float2bfloat16(v.z);
    __nv_bfloat16 h3 = __float2bfloat16(v.w);
    __nv_bfloat16 l0 = __float2bfloat16(v.x - __bfloat162float(h0));
    __nv_bfloat16 l1 = __float2bfloat16(v.y - __bfloat162float(h1));
    __nv_bfloat16 l2 = __float2bfloat16(v.z - __bfloat162float(h2));
    __nv_bfloat16 l3 = __float2bfloat16(v.w - __bfloat162float(h3));
    __nv_bfloat162 ph0; ph0.x = h0; ph0.y = h1;
    __nv_bfloat162 ph1; ph1.x = h2; ph1.y = h3;
    __nv_bfloat162 pl0; pl0.x = l0; pl0.y = l1;
    __nv_bfloat162 pl1; pl1.x = l2; pl1.y = l3;
    *(__nv_bfloat162*)(h + i)     = ph0;
    *(__nv_bfloat162*)(h + i + 2) = ph1;
    *(__nv_bfloat162*)(l + i)     = pl0;
    *(__nv_bfloat162*)(l + i + 2) = pl1;
}

// ---------------------------------------------------------------------------
// HMMA GEMM (as R6).  mode 0/1/2: write Q/K/V bf16 hi/lo head-transposed
// (Q pre-scaled by 0.125).  mode 3: write Cp fp32 row-major.
// ---------------------------------------------------------------------------
#define OPB   18432                       // 128 rows * 144 B
#define STG   (4 * OPB)                   // Ah, Al, Bh, Bl = 73728
#define GEMM_SMEM (2 * STG)               // 147456

__global__ __launch_bounds__(256, 1)
void gemm_hmma(const float* __restrict__ bias, float* __restrict__ Cp, int mode)
{
    extern __shared__ char smraw[];
    const uint32_t sb = smaddr(smraw);

    const int tid  = threadIdx.x;
    const int wid  = tid >> 5;
    const int lane = tid & 31;
    const int n0   = blockIdx.x << 7;
    const int m0   = blockIdx.y << 7;

    const int widx = (mode == 3) ? 3 : mode;
    const __nv_bfloat16* Ah = (mode == 3) ? g_ah : g_xh;
    const __nv_bfloat16* Al = (mode == 3) ? g_al : g_xl;
    const __nv_bfloat16* Bh = g_wh[widx];
    const __nv_bfloat16* Bl = g_wl[widx];

    float acc[2][8][4];
#pragma unroll
    for (int mi = 0; mi < 2; mi++)
#pragma unroll
        for (int nj = 0; nj < 8; nj++)
#pragma unroll
            for (int e = 0; e < 4; e++) acc[mi][nj][e] = 0.f;

    const int lr = tid >> 3;
    const int lu = tid & 7;

    const int wm  = wid & 3;
    const int wn  = wid >> 2;
    const int rl  = lane & 7;
    const int seg = lane >> 3;
    const uint32_t a_off =
        (uint32_t)((wm * 32 + rl + (seg & 1) * 8) * 144 + ((seg >> 1) * 8) * 2);
    const uint32_t b_off =
        (uint32_t)((wn * 64 + rl + (seg & 1) * 8) * 144 + ((seg >> 1) * 8) * 2);

    {
        const uint32_t stg = sb;
#pragma unroll
        for (int i = 0; i < 4; i++) {
            const int r = lr + 32 * i;
            const uint32_t dofs = (uint32_t)(r * 144 + lu * 16);
            cpa16(stg + 0 * OPB + dofs, Ah + (size_t)(m0 + r) * DIM + lu * 8);
            cpa16(stg + 1 * OPB + dofs, Al + (size_t)(m0 + r) * DIM + lu * 8);
            cpa16(stg + 2 * OPB + dofs, Bh + (size_t)(n0 + r) * DIM + lu * 8);
            cpa16(stg + 3 * OPB + dofs, Bl + (size_t)(n0 + r) * DIM + lu * 8);
        }
        asm volatile("cp.async.commit_group;" ::: "memory");
    }

    for (int c = 0; c < 16; c++) {
        if (c + 1 < 16) {
            const uint32_t stg = sb + (uint32_t)((c + 1) & 1) * STG;
            const int k0 = (c + 1) << 6;
#pragma unroll
            for (int i = 0; i < 4; i++) {
                const int r = lr + 32 * i;
                const uint32_t dofs = (uint32_t)(r * 144 + lu * 16);
                cpa16(stg + 0 * OPB + dofs, Ah + (size_t)(m0 + r) * DIM + k0 + lu * 8);
                cpa16(stg + 1 * OPB + dofs, Al + (size_t)(m0 + r) * DIM + k0 + lu * 8);
                cpa16(stg + 2 * OPB + dofs, Bh + (size_t)(n0 + r) * DIM + k0 + lu * 8);
                cpa16(stg + 3 * OPB + dofs, Bl + (size_t)(n0 + r) * DIM + k0 + lu * 8);
            }
            asm volatile("cp.async.commit_group;" ::: "memory");
            asm volatile("cp.async.wait_group 1;" ::: "memory");
        } else {
            asm volatile("cp.async.wait_group 0;" ::: "memory");
        }
        __syncthreads();

        const uint32_t stg = sb + (uint32_t)(c & 1) * STG;
#pragma unroll
        for (int ks = 0; ks < 4; ks++) {
            uint32_t fah[2][4], fal[2][4];
#pragma unroll
            for (int mi = 0; mi < 2; mi++) {
                ldsm4(fah[mi], stg + 0 * OPB + a_off + mi * 2304 + ks * 32);
                ldsm4(fal[mi], stg + 1 * OPB + a_off + mi * 2304 + ks * 32);
            }
            uint32_t fbh[4][4], fbl[4][4];
#pragma unroll
            for (int bj = 0; bj < 4; bj++) {
                ldsm4(fbh[bj], stg + 2 * OPB + b_off + bj * 2304 + ks * 32);
                ldsm4(fbl[bj], stg + 3 * OPB + b_off + bj * 2304 + ks * 32);
            }
#pragma unroll
            for (int mi = 0; mi < 2; mi++)
#pragma unroll
                for (int bj = 0; bj < 4; bj++) {
                    mma_bf16(acc[mi][2 * bj + 0], fah[mi], fbh[bj][0], fbh[bj][2]);
                    mma_bf16(acc[mi][2 * bj + 1], fah[mi], fbh[bj][1], fbh[bj][3]);
                    mma_bf16(acc[mi][2 * bj + 0], fah[mi], fbl[bj][0], fbl[bj][2]);
                    mma_bf16(acc[mi][2 * bj + 1], fah[mi], fbl[bj][1], fbl[bj][3]);
                    mma_bf16(acc[mi][2 * bj + 0], fal[mi], fbh[bj][0], fbh[bj][2]);
                    mma_bf16(acc[mi][2 * bj + 1], fal[mi], fbh[bj][1], fbh[bj][3]);
                }
        }
        __syncthreads();
    }

    // ---- epilogue ----
    const int qrow = lane >> 2;
    const int qcol = (lane & 3) << 1;
    const float qscale = (mode == 0) ? 0.125f : 1.0f;
    __nv_bfloat16* Gh = (mode == 0) ? g_Qh : (mode == 1) ? g_Kh : g_Vh;
    __nv_bfloat16* Gl = (mode == 0) ? g_Ql : (mode == 1) ? g_Kl : g_Vl;
#pragma unroll
    for (int mi = 0; mi < 2; mi++) {
#pragma unroll
        for (int nj = 0; nj < 8; nj++) {
            const int col = n0 + wn * 64 + nj * 8 + qcol;
            const float2 bv = *(const float2*)&bias[col];
            const int mrow = m0 + wm * 32 + mi * 16 + qrow;
#pragma unroll
            for (int half = 0; half < 2; half++) {
                const int m = mrow + half * 8;
                float ox = acc[mi][nj][2 * half + 0] + bv.x;
                float oy = acc[mi][nj][2 * half + 1] + bv.y;
                if (mode == 3) {
                    float2 o; o.x = ox; o.y = oy;
                    *(float2*)&Cp[(size_t)m * DIM + col] = o;
                } else {
                    ox *= qscale; oy *= qscale;
                    const int h    = col >> 6;
                    const int dh   = col & 63;
                    const int bidx = m >> 11;
                    const int nn   = m & (SEQ - 1);
                    const size_t base =
                        ((size_t)(bidx * HEADS + h) * SEQ + nn) * HDIM + dh;
                    __nv_bfloat16 hx = __float2bfloat16(ox);
                    __nv_bfloat16 hy = __float2bfloat16(oy);
                    __nv_bfloat162 ph; ph.x = hx; ph.y = hy;
                    __nv_bfloat162 pl;
                    pl.x = __float2bfloat16(ox - __bfloat162float(hx));
                    pl.y = __float2bfloat16(oy - __bfloat162float(hy));
                    *(__nv_bfloat162*)&Gh[base] = ph;
                    *(__nv_bfloat162*)&Gl[base] = pl;
                }
            }
        }
    }
}

// ---------------------------------------------------------------------------
// HMMA flash attention. CTA = (b, h, 64-q-tile), 128 threads (4 warps x 16 q
// rows). Q frags register-resident; K/V bf16 hi/lo double-buffered cp.async.
// S = QhKh+QhKl+QlKh; P split in-register; O += PhVh+PhVl+PlVh.
// ---------------------------------------------------------------------------
#define AQ_OFF   0
#define AQ_SZ    9216                     // 64 rows * 144 B
#define AST_OFF  (2 * AQ_SZ)              // 18432: stage region
#define AKH      0
#define AKL      9216
#define AVH      18432
#define AVL      27648
#define AMSK     36864
#define ASTAGE   37120                    // stage stride (64B mask + pad)
#define ATTN_SMEM (AST_OFF + 2 * ASTAGE)  // 92672

__global__ __launch_bounds__(128, 1)
void attn_hmma(const unsigned char* __restrict__ mask)
{
    extern __shared__ char smraw[];
    const uint32_t sb = smaddr(smraw);

    const int qt  = blockIdx.x;
    const int h   = blockIdx.y;
    const int b   = blockIdx.z;
    const int tid = threadIdx.x;
    const int wid = tid >> 5;
    const int lane = tid & 31;
    const int rl  = lane & 7;
    const int seg = lane >> 3;

    const size_t bh = (size_t)(b * HEADS + h) * SEQ * HDIM;
    const unsigned char* mg = mask + b * SEQ;

    // ---- loader indices: each thread does 4 rows x 1 unit per matrix ----
    const int lu = tid & 7;          // 16B unit (8 bf16)
    const int lr = tid >> 3;         // row base 0..15

    // ---- prologue: load Q (hi/lo) + stage0 (chunk 0) ----
    {
        const int qb = qt << 6;
#pragma unroll
        for (int i = 0; i < 4; i++) {
            const int r = lr + 16 * i;
            const uint32_t dofs = (uint32_t)(r * 144 + lu * 16);
            cpa16(sb + AQ_OFF + dofs,        g_Qh + bh + (size_t)(qb + r) * HDIM + lu * 8);
            cpa16(sb + AQ_OFF + AQ_SZ + dofs, g_Ql + bh + (size_t)(qb + r) * HDIM + lu * 8);
            cpa16(sb + AST_OFF + AKH + dofs, g_Kh + bh + (size_t)r * HDIM + lu * 8);
            cpa16(sb + AST_OFF + AKL + dofs, g_Kl + bh + (size_t)r * HDIM + lu * 8);
            cpa16(sb + AST_OFF + AVH + dofs, g_Vh + bh + (size_t)r * HDIM + lu * 8);
            cpa16(sb + AST_OFF + AVL + dofs, g_Vl + bh + (size_t)r * HDIM + lu * 8);
        }
        if (tid < 4) cpa16(sb + AST_OFF + AMSK + tid * 16, mg + tid * 16);
        asm volatile("cp.async.commit_group;" ::: "memory");
        asm volatile("cp.async.wait_group 0;" ::: "memory");
        __syncthreads();
    }

    // ---- Q fragments (register-resident) ----
    uint32_t qh[4][4], ql[4][4];
    {
        const uint32_t qa = sb + AQ_OFF +
            (uint32_t)((wid * 16 + rl + (seg & 1) * 8) * 144 + (seg >> 1) * 16);
#pragma unroll
        for (int ks = 0; ks < 4; ks++) {
            ldsm4(qh[ks], qa + ks * 32);
            ldsm4(ql[ks], qa + AQ_SZ + ks * 32);
        }
    }

    float oacc[8][4];
#pragma unroll
    for (int nf = 0; nf < 8; nf++)
#pragma unroll
        for (int e = 0; e < 4; e++) oacc[nf][e] = 0.f;
    float mr0 = -1e30f, mr1 = -1e30f, lr0 = 0.f, lr1 = 0.f;

    // fragment smem offsets (within a stage)
    const uint32_t kfo = (uint32_t)((rl + (seg & 1) * 8) * 144 + (seg >> 1) * 16);
    const uint32_t vfo = kfo;   // same lane pattern; row = kpos, col bytes via np

    for (int kt = 0; kt < SEQ / 64; kt++) {
        const uint32_t stg = sb + AST_OFF + (uint32_t)(kt & 1) * ASTAGE;

        // prefetch next chunk into the other stage
        if (kt + 1 < SEQ / 64) {
            const uint32_t stn = sb + AST_OFF + (uint32_t)((kt + 1) & 1) * ASTAGE;
            const int kb = (kt + 1) << 6;
#pragma unroll
            for (int i = 0; i < 4; i++) {
                const int r = lr + 16 * i;
                const uint32_t dofs = (uint32_t)(r * 144 + lu * 16);
                cpa16(stn + AKH + dofs, g_Kh + bh + (size_t)(kb + r) * HDIM + lu * 8);
                cpa16(stn + AKL + dofs, g_Kl + bh + (size_t)(kb + r) * HDIM + lu * 8);
                cpa16(stn + AVH + dofs, g_Vh + bh + (size_t)(kb + r) * HDIM + lu * 8);
                cpa16(stn + AVL + dofs, g_Vl + bh + (size_t)(kb + r) * HDIM + lu * 8);
            }
            if (tid < 4) cpa16(stn + AMSK + tid * 16, mg + kb + tid * 16);
            asm volatile("cp.async.commit_group;" ::: "memory");
        }

        // ---- S = Q K^T (hi/lo split) ----
        float sacc[8][4];
#pragma unroll
        for (int nf = 0; nf < 8; nf++)
#pragma unroll
            for (int e = 0; e < 4; e++) sacc[nf][e] = 0.f;

#pragma unroll
        for (int ks = 0; ks < 4; ks++) {
#pragma unroll
            for (int np = 0; np < 4; np++) {
                const uint32_t ka = stg + (uint32_t)(np * 16 * 144 + ks * 32) + kfo;
                uint32_t bh4[4], bl4[4];
                ldsm4(bh4, ka + AKH);
                ldsm4(bl4, ka + AKL);
                const int j0 = 2 * np, j1 = 2 * np + 1;
                mma_bf16(sacc[j0], qh[ks], bh4[0], bh4[2]);
                mma_bf16(sacc[j1], qh[ks], bh4[1], bh4[3]);
                mma_bf16(sacc[j0], qh[ks], bl4[0], bl4[2]);
                mma_bf16(sacc[j1], qh[ks], bl4[1], bl4[3]);
                mma_bf16(sacc[j0], ql[ks], bh4[0], bh4[2]);
                mma_bf16(sacc[j1], ql[ks], bh4[1], bh4[3]);
            }
        }

        // ---- mask + online softmax ----
        float mx0 = -1e30f, mx1 = -1e30f;
#pragma unroll
        for (int nf = 0; nf < 8; nf++) {
            const uint32_t mm = ldsu16(stg + AMSK + (uint32_t)(nf * 8 + 2 * (lane & 3)));
            if (mm & 0x00FFu)  { sacc[nf][0] = -20000.f; sacc[nf][2] = -20000.f; }
            if (mm & 0xFF00u)  { sacc[nf][1] = -20000.f; sacc[nf][3] = -20000.f; }
            mx0 = fmaxf(mx0, fmaxf(sacc[nf][0], sacc[nf][1]));
            mx1 = fmaxf(mx1, fmaxf(sacc[nf][2], sacc[nf][3]));
        }
        mx0 = fmaxf(mx0, __shfl_xor_sync(0xffffffffu, mx0, 1));
        mx0 = fmaxf(mx0, __shfl_xor_sync(0xffffffffu, mx0, 2));
        mx1 = fmaxf(mx1, __shfl_xor_sync(0xffffffffu, mx1, 1));
        mx1 = fmaxf(mx1, __shfl_xor_sync(0xffffffffu, mx1, 2));
        const float mn0 = fmaxf(mr0, mx0);
        const float mn1 = fmaxf(mr1, mx1);
        const float a0 = __expf(mr0 - mn0);
        const float a1 = __expf(mr1 - mn1);
        float ls0 = 0.f, ls1 = 0.f;
#pragma unroll
        for (int nf = 0; nf < 8; nf++) {
            sacc[nf][0] = __expf(sacc[nf][0] - mn0);
            sacc[nf][1] = __expf(sacc[nf][1] - mn0);
            sacc[nf][2] = __expf(sacc[nf][2] - mn1);
            sacc[nf][3] = __expf(sacc[nf][3] - mn1);
            ls0 += sacc[nf][0] + sacc[nf][1];
            ls1 += sacc[nf][2] + sacc[nf][3];
        }
        lr0 = lr0 * a0 + ls0;
        lr1 = lr1 * a1 + ls1;
        mr0 = mn0; mr1 = mn1;
#pragma unroll
        for (int nf = 0; nf < 8; nf++) {
            oacc[nf][0] *= a0; oacc[nf][1] *= a0;
            oacc[nf][2] *= a1; oacc[nf][3] *= a1;
        }

        // ---- O += P V (P split in-register) ----
#pragma unroll
        for (int ks = 0; ks < 4; ks++) {
            const float* f0 = sacc[2 * ks];
            const float* f1 = sacc[2 * ks + 1];
            uint32_t ah4[4], al4[4];
#pragma unroll
            for (int e = 0; e < 4; e++) {
                const float px = (e < 2) ? f0[2 * e]     : f1[2 * (e - 2)];
                const float py = (e < 2) ? f0[2 * e + 1] : f1[2 * (e - 2) + 1];
                const __nv_bfloat16 hx = __float2bfloat16(px);
                const __nv_bfloat16 hy = __float2bfloat16(py);
                __nv_bfloat162 pp; pp.x = hx; pp.y = hy;
                ah4[e] = *(const uint32_t*)&pp;
                al4[e] = packbf(px - __bfloat162float(hx),
                                py - __bfloat162float(hy));
            }
            // NOTE: a-frag order must be (a0: row r k0-7, a1: row r+8 k0-7,
            // a2: row r k8-15, a3: row r+8 k8-15):
            // f0 covers kpos 8-block (cols 2t,2t+1 of frag 2ks) -> k0-7 half,
            // rows r (x,y -> e order ok) / r+8 (z,w).
            // Reorder: ah4 built as [f0 row r, f0 row r+8, f1 row r, f1 row r+8] ✓
#pragma unroll
            for (int np = 0; np < 4; np++) {
                const uint32_t va = stg + (uint32_t)(ks * 16 * 144 + np * 32) + vfo;
                uint32_t vh4[4], vl4[4];
                ldsm4t(vh4, va + AVH);
                ldsm4t(vl4, va + AVL);
                const int j0 = 2 * np, j1 = 2 * np + 1;
                mma_bf16(oacc[j0], ah4, vh4[0], vh4[1]);
                mma_bf16(oacc[j1], ah4, vh4[2], vh4[3]);
                mma_bf16(oacc[j0], ah4, vl4[0], vl4[1]);
                mma_bf16(oacc[j1], ah4, vl4[2], vl4[3]);
                mma_bf16(oacc[j0], al4, vh4[0], vh4[1]);
                mma_bf16(oacc[j1], al4, vh4[2], vh4[3]);
            }
        }

        if (kt + 1 < SEQ / 64)
            asm volatile("cp.async.wait_group 0;" ::: "memory");
        __syncthreads();
    }

    // ---- finalize: l-reduce across quartet, normalize, store ----
    float l0 = lr0, l1 = lr1;
    l0 += __shfl_xor_sync(0xffffffffu, l0, 1);
    l0 += __shfl_xor_sync(0xffffffffu, l0, 2);
    l1 += __shfl_xor_sync(0xffffffffu, l1, 1);
    l1 += __shfl_xor_sync(0xffffffffu, l1, 2);
    const float i0 = 1.f / l0, i1 = 1.f / l1;

    const int r0 = qt * 64 + wid * 16 + (lane >> 2);
    const int r1 = r0 + 8;
    const int cb = h * 64 + 2 * (lane & 3);
    float* O0 = g_Att + (size_t)(b * SEQ + r0) * DIM + cb;
    float* O1 = g_Att + (size_t)(b * SEQ + r1) * DIM + cb;
#pragma unroll
    for (int nf = 0; nf < 8; nf++) {
        float2 v0; v0.x = oacc[nf][0] * i0; v0.y = oacc[nf][1] * i0;
        float2 v1; v1.x = oacc[nf][2] * i1; v1.y = oacc[nf][3] * i1;
        *(float2*)(O0 + nf * 8) = v0;
        *(float2*)(O1 + nf * 8) = v1;
    }
}

// ---------------------------------------------------------------------------
extern "C" void kernel_launch(void* const* d_in, const int* in_sizes, int n_in,
                              void* d_out, int out_size)
{
    const float* x          = (const float*)d_in[0];
    const unsigned char* mk = (const unsigned char*)d_in[1];
    const float* Wq = (const float*)d_in[2];
    const float* bq = (const float*)d_in[3];
    const float* Wk = (const float*)d_in[4];
    const float* bk = (const float*)d_in[5];
    const float* Wv = (const float*)d_in[6];
    const float* bv = (const float*)d_in[7];
    const float* Wo = (const float*)d_in[8];
    const float* bo = (const float*)d_in[9];
    float* out = (float*)d_out;

    cudaFuncSetAttribute(gemm_hmma, cudaFuncAttributeMaxDynamicSharedMemorySize,
                         GEMM_SMEM);
    cudaFuncSetAttribute(attn_hmma, cudaFuncAttributeMaxDynamicSharedMemorySize,
                         ATTN_SMEM);

    split_bf16<<<MROWS * DIM / 1024, 256>>>(x,  0);
    split_bf16<<<DIM * DIM / 1024,  256>>>(Wq, 1);
    split_bf16<<<DIM * DIM / 1024,  256>>>(Wk, 2);
    split_bf16<<<DIM * DIM / 1024,  256>>>(Wv, 3);
    split_bf16<<<DIM * DIM / 1024,  256>>>(Wo, 4);

    dim3 gg(DIM / 128, MROWS / 128);   // (8, 32)
    gemm_hmma<<<gg, 256, GEMM_SMEM>>>(bq, out, 0);
    gemm_hmma<<<gg, 256, GEMM_SMEM>>>(bk, out, 1);
    gemm_hmma<<<gg, 256, GEMM_SMEM>>>(bv, out, 2);

    attn_hmma<<<dim3(SEQ / 64, HEADS, BATCH), 128, ATTN_SMEM>>>(mk);

    split_bf16<<<MROWS * DIM / 1024, 256>>>(nullptr, 5);
    gemm_hmma<<<gg, 256, GEMM_SMEM>>>(bo, out, 3);
}

// round 14
// speedup vs baseline: 3.1732x; 1.0283x over previous
#include <cuda_runtime.h>
#include <cuda_bf16.h>
#include <cstdint>

// ---------------------------------------------------------------------------
// MultiheadSelfAttention: B=2, N=2048, D=1024, H=16, hd=64, fp32.
// R13: R11 with the GEMM smem stride fixed 72 -> 80 B (16B alignment for
// cp.async/ldmatrix; 72 made odd rows 8-mod-16 -> misaligned address).
//  - GEMM: K-chunk 32, smem 80KB, 2 CTAs/SM -> single wave (256 CTAs).
//  - Attention: Q staged through the kt=1 buffer, smem 74.2KB -> 3 CTAs/SM.
//  - Attention epilogue writes g_ah/g_al (hi/lo) directly; no g_Att.
//  - One fused split_all pre-pass for x + 4 weights.
// ---------------------------------------------------------------------------

#define BATCH   2
#define SEQ     2048
#define DIM     1024
#define HEADS   16
#define HDIM    64
#define MROWS   (BATCH * SEQ)            // 4096

// bf16 hi/lo split scratch
__device__ __nv_bfloat16 g_xh[MROWS * DIM], g_xl[MROWS * DIM];
__device__ __nv_bfloat16 g_wh[4][DIM * DIM], g_wl[4][DIM * DIM];
__device__ __nv_bfloat16 g_ah[MROWS * DIM], g_al[MROWS * DIM];
// Q/K/V as bf16 hi/lo, head-transposed [B*H][SEQ][64]
#define QKVN (BATCH * HEADS * SEQ * HDIM)
__device__ __nv_bfloat16 g_Qh[QKVN], g_Ql[QKVN];
__device__ __nv_bfloat16 g_Kh[QKVN], g_Kl[QKVN];
__device__ __nv_bfloat16 g_Vh[QKVN], g_Vl[QKVN];

typedef unsigned long long u64;

// ---- helpers ---------------------------------------------------------------
__device__ __forceinline__ uint32_t smaddr(const void* p) {
    uint32_t r;
    asm("{ .reg .u64 t; cvta.to.shared.u64 t, %1; cvt.u32.u64 %0, t; }"
        : "=r"(r) : "l"(p));
    return r;
}
__device__ __forceinline__ void cpa16(uint32_t dst, const void* src) {
    asm volatile("cp.async.cg.shared.global [%0], [%1], 16;"
                 :: "r"(dst), "l"(src) : "memory");
}
__device__ __forceinline__ void ldsm4(uint32_t* r, uint32_t addr) {
    asm volatile("ldmatrix.sync.aligned.m8n8.x4.shared.b16 {%0,%1,%2,%3}, [%4];"
                 : "=r"(r[0]), "=r"(r[1]), "=r"(r[2]), "=r"(r[3]) : "r"(addr));
}
__device__ __forceinline__ void ldsm4t(uint32_t* r, uint32_t addr) {
    asm volatile("ldmatrix.sync.aligned.m8n8.x4.trans.shared.b16 {%0,%1,%2,%3}, [%4];"
                 : "=r"(r[0]), "=r"(r[1]), "=r"(r[2]), "=r"(r[3]) : "r"(addr));
}
__device__ __forceinline__ void mma_bf16(float* d, const uint32_t* a,
                                         uint32_t b0, uint32_t b1) {
    asm volatile(
        "mma.sync.aligned.m16n8k16.row.col.f32.bf16.bf16.f32 "
        "{%0,%1,%2,%3}, {%4,%5,%6,%7}, {%8,%9}, {%0,%1,%2,%3};"
        : "+f"(d[0]), "+f"(d[1]), "+f"(d[2]), "+f"(d[3])
        : "r"(a[0]), "r"(a[1]), "r"(a[2]), "r"(a[3]), "r"(b0), "r"(b1));
}
__device__ __forceinline__ uint32_t packbf(float x, float y) {
    uint32_t r;
    asm("cvt.rn.bf16x2.f32 %0, %1, %2;" : "=r"(r) : "f"(y), "f"(x));
    return r;
}
__device__ __forceinline__ uint32_t ldsu16(uint32_t a) {
    uint32_t r;
    asm volatile("ld.shared.u16 %0, [%1];" : "=r"(r) : "r"(a));
    return r;
}

// ---------------------------------------------------------------------------
// Fused bf16 hi/lo split: blocks 0..4095 -> x, then 1024 per weight.
// ---------------------------------------------------------------------------
__global__ void split_all(const float* __restrict__ x,
                          const float* __restrict__ Wq,
                          const float* __restrict__ Wk,
                          const float* __restrict__ Wv,
                          const float* __restrict__ Wo)
{
    const int bid = blockIdx.x;
    const float* s;
    __nv_bfloat16 *h, *l;
    int base;
    if (bid < 4096) { s = x; h = g_xh; l = g_xl; base = bid; }
    else {
        const int w  = (bid - 4096) >> 10;
        base = (bid - 4096) & 1023;
        s = (w == 0) ? Wq : (w == 1) ? Wk : (w == 2) ? Wv : Wo;
        h = g_wh[w]; l = g_wl[w];
    }
    const int i = (base * 256 + threadIdx.x) << 2;
    float4 v = *(const float4*)(s + i);
    __nv_bfloat16 h0 = __float2bfloat16(v.x);
    __nv_bfloat16 h1 = __float2bfloat16(v.y);
    __nv_bfloat16 h2 = __float2bfloat16(v.z);
    __nv_bfloat16 h3 = __float2bfloat16(v.w);
    __nv_bfloat162 ph0; ph0.x = h0; ph0.y = h1;
    __nv_bfloat162 ph1; ph1.x = h2; ph1.y = h3;
    __nv_bfloat162 pl0;
    pl0.x = __float2bfloat16(v.x - __bfloat162float(h0));
    pl0.y = __float2bfloat16(v.y - __bfloat162float(h1));
    __nv_bfloat162 pl1;
    pl1.x = __float2bfloat16(v.z - __bfloat162float(h2));
    pl1.y = __float2bfloat16(v.w - __bfloat162float(h3));
    *(__nv_bfloat162*)(h + i)     = ph0;
    *(__nv_bfloat162*)(h + i + 2) = ph1;
    *(__nv_bfloat162*)(l + i)     = pl0;
    *(__nv_bfloat162*)(l + i + 2) = pl1;
}

// ---------------------------------------------------------------------------
// HMMA GEMM, K-chunk 32, 2 CTAs/SM.  C = AhBh + AhBl + AlBh (+bias).
// mode 0/1/2: write Q/K/V bf16 hi/lo head-transposed (Q pre-scaled 0.125).
// mode 3:     A = attention-output split, write Cp fp32 row-major.
// Row stride 80 B (= 5*16: 16B-aligned rows; banks 20r mod 32 -> all 32
// banks covered once per 8-row ldmatrix phase, conflict-free).
// ---------------------------------------------------------------------------
#define OPB   10240                       // 128 rows * 80 B
#define STG   (4 * OPB)                   // Ah, Al, Bh, Bl = 40960
#define GEMM_SMEM (2 * STG)               // 81920

__global__ __launch_bounds__(256, 2)
void gemm_hmma(const float* __restrict__ bias, float* __restrict__ Cp, int mode)
{
    extern __shared__ char smraw[];
    const uint32_t sb = smaddr(smraw);

    const int tid  = threadIdx.x;
    const int wid  = tid >> 5;
    const int lane = tid & 31;
    const int n0   = blockIdx.x << 7;
    const int m0   = blockIdx.y << 7;

    const int widx = (mode == 3) ? 3 : mode;
    const __nv_bfloat16* Ah = (mode == 3) ? g_ah : g_xh;
    const __nv_bfloat16* Al = (mode == 3) ? g_al : g_xl;
    const __nv_bfloat16* Bh = g_wh[widx];
    const __nv_bfloat16* Bl = g_wl[widx];

    float acc[2][8][4];
#pragma unroll
    for (int mi = 0; mi < 2; mi++)
#pragma unroll
        for (int nj = 0; nj < 8; nj++)
#pragma unroll
            for (int e = 0; e < 4; e++) acc[mi][nj][e] = 0.f;

    const int lr = tid >> 2;      // 0..63
    const int lu = tid & 3;       // 16B unit within 64B row

    const int wm  = wid & 3;
    const int wn  = wid >> 2;
    const int rl  = lane & 7;
    const int seg = lane >> 3;
    const uint32_t a_off =
        (uint32_t)((wm * 32 + rl + (seg & 1) * 8) * 80 + (seg >> 1) * 16);
    const uint32_t b_off =
        (uint32_t)((wn * 64 + rl + (seg & 1) * 8) * 80 + (seg >> 1) * 16);

    // prologue: stage 0 <- chunk 0
    {
        const uint32_t stg = sb;
#pragma unroll
        for (int i = 0; i < 2; i++) {
            const int r = lr + 64 * i;
            const uint32_t dofs = (uint32_t)(r * 80 + lu * 16);
            cpa16(stg + 0 * OPB + dofs, Ah + (size_t)(m0 + r) * DIM + lu * 8);
            cpa16(stg + 1 * OPB + dofs, Al + (size_t)(m0 + r) * DIM + lu * 8);
            cpa16(stg + 2 * OPB + dofs, Bh + (size_t)(n0 + r) * DIM + lu * 8);
            cpa16(stg + 3 * OPB + dofs, Bl + (size_t)(n0 + r) * DIM + lu * 8);
        }
        asm volatile("cp.async.commit_group;" ::: "memory");
    }

    for (int c = 0; c < 32; c++) {
        if (c + 1 < 32) {
            const uint32_t stg = sb + (uint32_t)((c + 1) & 1) * STG;
            const int k0 = (c + 1) << 5;
#pragma unroll
            for (int i = 0; i < 2; i++) {
                const int r = lr + 64 * i;
                const uint32_t dofs = (uint32_t)(r * 80 + lu * 16);
                cpa16(stg + 0 * OPB + dofs, Ah + (size_t)(m0 + r) * DIM + k0 + lu * 8);
                cpa16(stg + 1 * OPB + dofs, Al + (size_t)(m0 + r) * DIM + k0 + lu * 8);
                cpa16(stg + 2 * OPB + dofs, Bh + (size_t)(n0 + r) * DIM + k0 + lu * 8);
                cpa16(stg + 3 * OPB + dofs, Bl + (size_t)(n0 + r) * DIM + k0 + lu * 8);
            }
            asm volatile("cp.async.commit_group;" ::: "memory");
            asm volatile("cp.async.wait_group 1;" ::: "memory");
        } else {
            asm volatile("cp.async.wait_group 0;" ::: "memory");
        }
        __syncthreads();

        const uint32_t stg = sb + (uint32_t)(c & 1) * STG;
#pragma unroll
        for (int ks = 0; ks < 2; ks++) {
            uint32_t fah[2][4], fal[2][4];
#pragma unroll
            for (int mi = 0; mi < 2; mi++) {
                ldsm4(fah[mi], stg + 0 * OPB + a_off + mi * 1280 + ks * 32);
                ldsm4(fal[mi], stg + 1 * OPB + a_off + mi * 1280 + ks * 32);
            }
#pragma unroll
            for (int bj = 0; bj < 4; bj++) {
                uint32_t bh4[4], bl4[4];
                ldsm4(bh4, stg + 2 * OPB + b_off + bj * 1280 + ks * 32);
                ldsm4(bl4, stg + 3 * OPB + b_off + bj * 1280 + ks * 32);
#pragma unroll
                for (int mi = 0; mi < 2; mi++) {
                    mma_bf16(acc[mi][2 * bj + 0], fah[mi], bh4[0], bh4[2]);
                    mma_bf16(acc[mi][2 * bj + 1], fah[mi], bh4[1], bh4[3]);
                    mma_bf16(acc[mi][2 * bj + 0], fah[mi], bl4[0], bl4[2]);
                    mma_bf16(acc[mi][2 * bj + 1], fah[mi], bl4[1], bl4[3]);
                    mma_bf16(acc[mi][2 * bj + 0], fal[mi], bh4[0], bh4[2]);
                    mma_bf16(acc[mi][2 * bj + 1], fal[mi], bh4[1], bh4[3]);
                }
            }
        }
        __syncthreads();
    }

    // ---- epilogue ----
    const int qrow = lane >> 2;
    const int qcol = (lane & 3) << 1;
    const float qscale = (mode == 0) ? 0.125f : 1.0f;
    __nv_bfloat16* Gh = (mode == 0) ? g_Qh : (mode == 1) ? g_Kh : g_Vh;
    __nv_bfloat16* Gl = (mode == 0) ? g_Ql : (mode == 1) ? g_Kl : g_Vl;
#pragma unroll
    for (int mi = 0; mi < 2; mi++) {
#pragma unroll
        for (int nj = 0; nj < 8; nj++) {
            const int col = n0 + wn * 64 + nj * 8 + qcol;
            const float2 bv = *(const float2*)&bias[col];
            const int mrow = m0 + wm * 32 + mi * 16 + qrow;
#pragma unroll
            for (int half = 0; half < 2; half++) {
                const int m = mrow + half * 8;
                float ox = acc[mi][nj][2 * half + 0] + bv.x;
                float oy = acc[mi][nj][2 * half + 1] + bv.y;
                if (mode == 3) {
                    float2 o; o.x = ox; o.y = oy;
                    *(float2*)&Cp[(size_t)m * DIM + col] = o;
                } else {
                    ox *= qscale; oy *= qscale;
                    const int h    = col >> 6;
                    const int dh   = col & 63;
                    const int bidx = m >> 11;
                    const int nn   = m & (SEQ - 1);
                    const size_t base =
                        ((size_t)(bidx * HEADS + h) * SEQ + nn) * HDIM + dh;
                    __nv_bfloat16 hx = __float2bfloat16(ox);
                    __nv_bfloat16 hy = __float2bfloat16(oy);
                    __nv_bfloat162 ph; ph.x = hx; ph.y = hy;
                    __nv_bfloat162 pl;
                    pl.x = __float2bfloat16(ox - __bfloat162float(hx));
                    pl.y = __float2bfloat16(oy - __bfloat162float(hy));
                    *(__nv_bfloat162*)&Gh[base] = ph;
                    *(__nv_bfloat162*)&Gl[base] = pl;
                }
            }
        }
    }
}

// ---------------------------------------------------------------------------
// HMMA flash attention. CTA = (b, h, 64-q-tile), 128 threads, 3 CTAs/SM.
// Q staged through the kt=1 K/V buffer (frags to regs), then overwritten.
// Epilogue writes g_ah/g_al hi/lo split directly.
// ---------------------------------------------------------------------------
#define AKH      0
#define AKL      9216
#define AVH      18432
#define AVL      27648
#define AMSK     36864
#define ASTAGE   37120
#define ATTN_SMEM (2 * ASTAGE)            // 74240

__global__ __launch_bounds__(128, 3)
void attn_hmma(const unsigned char* __restrict__ mask)
{
    extern __shared__ char smraw[];
    const uint32_t sb = smaddr(smraw);

    const int qt  = blockIdx.x;
    const int h   = blockIdx.y;
    const int b   = blockIdx.z;
    const int tid = threadIdx.x;
    const int wid = tid >> 5;
    const int lane = tid & 31;
    const int rl  = lane & 7;
    const int seg = lane >> 3;

    const size_t bh = (size_t)(b * HEADS + h) * SEQ * HDIM;
    const unsigned char* mg = mask + b * SEQ;

    const int lu = tid & 7;          // 16B unit (8 bf16) within 128B row
    const int lr = tid >> 3;         // row base 0..15

    const uint32_t st0 = sb;
    const uint32_t st1 = sb + ASTAGE;

    // ---- prologue: Q (hi/lo) -> stage1 K area; chunk 0 K/V -> stage0 ----
    {
        const int qb = qt << 6;
#pragma unroll
        for (int i = 0; i < 4; i++) {
            const int r = lr + 16 * i;
            const uint32_t dofs = (uint32_t)(r * 144 + lu * 16);
            cpa16(st1 + AKH + dofs, g_Qh + bh + (size_t)(qb + r) * HDIM + lu * 8);
            cpa16(st1 + AKL + dofs, g_Ql + bh + (size_t)(qb + r) * HDIM + lu * 8);
            cpa16(st0 + AKH + dofs, g_Kh + bh + (size_t)r * HDIM + lu * 8);
            cpa16(st0 + AKL + dofs, g_Kl + bh + (size_t)r * HDIM + lu * 8);
            cpa16(st0 + AVH + dofs, g_Vh + bh + (size_t)r * HDIM + lu * 8);
            cpa16(st0 + AVL + dofs, g_Vl + bh + (size_t)r * HDIM + lu * 8);
        }
        if (tid < 4) cpa16(st0 + AMSK + tid * 16, mg + tid * 16);
        asm volatile("cp.async.commit_group;" ::: "memory");
        asm volatile("cp.async.wait_group 0;" ::: "memory");
        __syncthreads();
    }

    // ---- Q fragments (register-resident), then release stage1 ----
    uint32_t qh[4][4], ql[4][4];
    {
        const uint32_t qa = st1 +
            (uint32_t)((wid * 16 + rl + (seg & 1) * 8) * 144 + (seg >> 1) * 16);
#pragma unroll
        for (int ks = 0; ks < 4; ks++) {
            ldsm4(qh[ks], qa + AKH + ks * 32);
            ldsm4(ql[ks], qa + AKL + ks * 32);
        }
    }
    __syncthreads();   // all warps done reading Q before stage1 is overwritten

    float oacc[8][4];
#pragma unroll
    for (int nf = 0; nf < 8; nf++)
#pragma unroll
        for (int e = 0; e < 4; e++) oacc[nf][e] = 0.f;
    float mr0 = -1e30f, mr1 = -1e30f, lr0 = 0.f, lr1 = 0.f;

    const uint32_t kfo = (uint32_t)((rl + (seg & 1) * 8) * 144 + (seg >> 1) * 16);
    const uint32_t vfo = kfo;

    for (int kt = 0; kt < SEQ / 64; kt++) {
        const uint32_t stg = sb + (uint32_t)(kt & 1) * ASTAGE;

        if (kt + 1 < SEQ / 64) {
            const uint32_t stn = sb + (uint32_t)((kt + 1) & 1) * ASTAGE;
            const int kb = (kt + 1) << 6;
#pragma unroll
            for (int i = 0; i < 4; i++) {
                const int r = lr + 16 * i;
                const uint32_t dofs = (uint32_t)(r * 144 + lu * 16);
                cpa16(stn + AKH + dofs, g_Kh + bh + (size_t)(kb + r) * HDIM + lu * 8);
                cpa16(stn + AKL + dofs, g_Kl + bh + (size_t)(kb + r) * HDIM + lu * 8);
                cpa16(stn + AVH + dofs, g_Vh + bh + (size_t)(kb + r) * HDIM + lu * 8);
                cpa16(stn + AVL + dofs, g_Vl + bh + (size_t)(kb + r) * HDIM + lu * 8);
            }
            if (tid < 4) cpa16(stn + AMSK + tid * 16, mg + kb + tid * 16);
            asm volatile("cp.async.commit_group;" ::: "memory");
        }

        // ---- S = Q K^T (hi/lo split) ----
        float sacc[8][4];
#pragma unroll
        for (int nf = 0; nf < 8; nf++)
#pragma unroll
            for (int e = 0; e < 4; e++) sacc[nf][e] = 0.f;

#pragma unroll
        for (int ks = 0; ks < 4; ks++) {
#pragma unroll
            for (int np = 0; np < 4; np++) {
                const uint32_t ka = stg + (uint32_t)(np * 16 * 144 + ks * 32) + kfo;
                uint32_t bh4[4], bl4[4];
                ldsm4(bh4, ka + AKH);
                ldsm4(bl4, ka + AKL);
                const int j0 = 2 * np, j1 = 2 * np + 1;
                mma_bf16(sacc[j0], qh[ks], bh4[0], bh4[2]);
                mma_bf16(sacc[j1], qh[ks], bh4[1], bh4[3]);
                mma_bf16(sacc[j0], qh[ks], bl4[0], bl4[2]);
                mma_bf16(sacc[j1], qh[ks], bl4[1], bl4[3]);
                mma_bf16(sacc[j0], ql[ks], bh4[0], bh4[2]);
                mma_bf16(sacc[j1], ql[ks], bh4[1], bh4[3]);
            }
        }

        // ---- mask + online softmax ----
        float mx0 = -1e30f, mx1 = -1e30f;
#pragma unroll
        for (int nf = 0; nf < 8; nf++) {
            const uint32_t mm = ldsu16(stg + AMSK + (uint32_t)(nf * 8 + 2 * (lane & 3)));
            if (mm & 0x00FFu)  { sacc[nf][0] = -20000.f; sacc[nf][2] = -20000.f; }
            if (mm & 0xFF00u)  { sacc[nf][1] = -20000.f; sacc[nf][3] = -20000.f; }
            mx0 = fmaxf(mx0, fmaxf(sacc[nf][0], sacc[nf][1]));
            mx1 = fmaxf(mx1, fmaxf(sacc[nf][2], sacc[nf][3]));
        }
        mx0 = fmaxf(mx0, __shfl_xor_sync(0xffffffffu, mx0, 1));
        mx0 = fmaxf(mx0, __shfl_xor_sync(0xffffffffu, mx0, 2));
        mx1 = fmaxf(mx1, __shfl_xor_sync(0xffffffffu, mx1, 1));
        mx1 = fmaxf(mx1, __shfl_xor_sync(0xffffffffu, mx1, 2));
        const float mn0 = fmaxf(mr0, mx0);
        const float mn1 = fmaxf(mr1, mx1);
        const float a0 = __expf(mr0 - mn0);
        const float a1 = __expf(mr1 - mn1);
        float ls0 = 0.f, ls1 = 0.f;
#pragma unroll
        for (int nf = 0; nf < 8; nf++) {
            sacc[nf][0] = __expf(sacc[nf][0] - mn0);
            sacc[nf][1] = __expf(sacc[nf][1] - mn0);
            sacc[nf][2] = __expf(sacc[nf][2] - mn1);
            sacc[nf][3] = __expf(sacc[nf][3] - mn1);
            ls0 += sacc[nf][0] + sacc[nf][1];
            ls1 += sacc[nf][2] + sacc[nf][3];
        }
        lr0 = lr0 * a0 + ls0;
        lr1 = lr1 * a1 + ls1;
        mr0 = mn0; mr1 = mn1;
#pragma unroll
        for (int nf = 0; nf < 8; nf++) {
            oacc[nf][0] *= a0; oacc[nf][1] *= a0;
            oacc[nf][2] *= a1; oacc[nf][3] *= a1;
        }

        // ---- O += P V (P split in-register) ----
#pragma unroll
        for (int ks = 0; ks < 4; ks++) {
            const float* f0 = sacc[2 * ks];
            const float* f1 = sacc[2 * ks + 1];
            uint32_t ah4[4], al4[4];
#pragma unroll
            for (int e = 0; e < 4; e++) {
                const float px = (e < 2) ? f0[2 * e]     : f1[2 * (e - 2)];
                const float py = (e < 2) ? f0[2 * e + 1] : f1[2 * (e - 2) + 1];
                const __nv_bfloat16 hx = __float2bfloat16(px);
                const __nv_bfloat16 hy = __float2bfloat16(py);
                __nv_bfloat162 pp; pp.x = hx; pp.y = hy;
                ah4[e] = *(const uint32_t*)&pp;
                al4[e] = packbf(px - __bfloat162float(hx),
                                py - __bfloat162float(hy));
            }
#pragma unroll
            for (int np = 0; np < 4; np++) {
                const uint32_t va = stg + (uint32_t)(ks * 16 * 144 + np * 32) + vfo;
                uint32_t vh4[4], vl4[4];
                ldsm4t(vh4, va + AVH);
                ldsm4t(vl4, va + AVL);
                const int j0 = 2 * np, j1 = 2 * np + 1;
                mma_bf16(oacc[j0], ah4, vh4[0], vh4[1]);
                mma_bf16(oacc[j1], ah4, vh4[2], vh4[3]);
                mma_bf16(oacc[j0], ah4, vl4[0], vl4[1]);
                mma_bf16(oacc[j1], ah4, vl4[2], vl4[3]);
                mma_bf16(oacc[j0], al4, vh4[0], vh4[1]);
                mma_bf16(oacc[j1], al4, vh4[2], vh4[3]);
            }
        }

        if (kt + 1 < SEQ / 64)
            asm volatile("cp.async.wait_group 0;" ::: "memory");
        __syncthreads();
    }

    // ---- finalize: quartet l-reduce, normalize, write hi/lo split ----
    float l0 = lr0, l1 = lr1;
    l0 += __shfl_xor_sync(0xffffffffu, l0, 1);
    l0 += __shfl_xor_sync(0xffffffffu, l0, 2);
    l1 += __shfl_xor_sync(0xffffffffu, l1, 1);
    l1 += __shfl_xor_sync(0xffffffffu, l1, 2);
    const float i0 = 1.f / l0, i1 = 1.f / l1;

    const int r0 = qt * 64 + wid * 16 + (lane >> 2);
    const int r1 = r0 + 8;
    const int cb = h * 64 + 2 * (lane & 3);
    const size_t o0 = (size_t)(b * SEQ + r0) * DIM + cb;
    const size_t o1 = (size_t)(b * SEQ + r1) * DIM + cb;
#pragma unroll
    for (int nf = 0; nf < 8; nf++) {
        const float v0x = oacc[nf][0] * i0, v0y = oacc[nf][1] * i0;
        const float v1x = oacc[nf][2] * i1, v1y = oacc[nf][3] * i1;
        __nv_bfloat16 h0x = __float2bfloat16(v0x), h0y = __float2bfloat16(v0y);
        __nv_bfloat16 h1x = __float2bfloat16(v1x), h1y = __float2bfloat16(v1y);
        __nv_bfloat162 p0h; p0h.x = h0x; p0h.y = h0y;
        __nv_bfloat162 p1h; p1h.x = h1x; p1h.y = h1y;
        __nv_bfloat162 p0l;
        p0l.x = __float2bfloat16(v0x - __bfloat162float(h0x));
        p0l.y = __float2bfloat16(v0y - __bfloat162float(h0y));
        __nv_bfloat162 p1l;
        p1l.x = __float2bfloat16(v1x - __bfloat162float(h1x));
        p1l.y = __float2bfloat16(v1y - __bfloat162float(h1y));
        *(__nv_bfloat162*)&g_ah[o0 + nf * 8] = p0h;
        *(__nv_bfloat162*)&g_al[o0 + nf * 8] = p0l;
        *(__nv_bfloat162*)&g_ah[o1 + nf * 8] = p1h;
        *(__nv_bfloat162*)&g_al[o1 + nf * 8] = p1l;
    }
}

// ---------------------------------------------------------------------------
extern "C" void kernel_launch(void* const* d_in, const int* in_sizes, int n_in,
                              void* d_out, int out_size)
{
    const float* x          = (const float*)d_in[0];
    const unsigned char* mk = (const unsigned char*)d_in[1];
    const float* Wq = (const float*)d_in[2];
    const float* bq = (const float*)d_in[3];
    const float* Wk = (const float*)d_in[4];
    const float* bk = (const float*)d_in[5];
    const float* Wv = (const float*)d_in[6];
    const float* bv = (const float*)d_in[7];
    const float* Wo = (const float*)d_in[8];
    const float* bo = (const float*)d_in[9];
    float* out = (float*)d_out;

    cudaFuncSetAttribute(gemm_hmma, cudaFuncAttributeMaxDynamicSharedMemorySize,
                         GEMM_SMEM);
    cudaFuncSetAttribute(attn_hmma, cudaFuncAttributeMaxDynamicSharedMemorySize,
                         ATTN_SMEM);

    split_all<<<8192, 256>>>(x, Wq, Wk, Wv, Wo);

    dim3 gg(DIM / 128, MROWS / 128);   // (8, 32)
    gemm_hmma<<<gg, 256, GEMM_SMEM>>>(bq, out, 0);
    gemm_hmma<<<gg, 256, GEMM_SMEM>>>(bk, out, 1);
    gemm_hmma<<<gg, 256, GEMM_SMEM>>>(bv, out, 2);

    attn_hmma<<<dim3(SEQ / 64, HEADS, BATCH), 128, ATTN_SMEM>>>(mk);

    gemm_hmma<<<gg, 256, GEMM_SMEM>>>(bo, out, 3);
}

// round 16
// speedup vs baseline: 3.2304x; 1.0180x over previous
#include <cuda_runtime.h>
#include <cuda_bf16.h>
#include <cstdint>

// ---------------------------------------------------------------------------
// MultiheadSelfAttention: B=2, N=2048, D=1024, H=16, hd=64, fp32.
// R15: R13 + GEMM mainloop term-pass reordering. The three split products
// (AhBh / AhBl / AlBh) now issue as three 16-MMA passes so each accumulator's
// dependent-reuse distance is 16 issues instead of 2 (tensor pipe was 41%
// busy, stalled on its own HMMA results). No addressing changes.
// ---------------------------------------------------------------------------

#define BATCH   2
#define SEQ     2048
#define DIM     1024
#define HEADS   16
#define HDIM    64
#define MROWS   (BATCH * SEQ)            // 4096

// bf16 hi/lo split scratch
__device__ __nv_bfloat16 g_xh[MROWS * DIM], g_xl[MROWS * DIM];
__device__ __nv_bfloat16 g_wh[4][DIM * DIM], g_wl[4][DIM * DIM];
__device__ __nv_bfloat16 g_ah[MROWS * DIM], g_al[MROWS * DIM];
// Q/K/V as bf16 hi/lo, head-transposed [B*H][SEQ][64]
#define QKVN (BATCH * HEADS * SEQ * HDIM)
__device__ __nv_bfloat16 g_Qh[QKVN], g_Ql[QKVN];
__device__ __nv_bfloat16 g_Kh[QKVN], g_Kl[QKVN];
__device__ __nv_bfloat16 g_Vh[QKVN], g_Vl[QKVN];

typedef unsigned long long u64;

// ---- helpers ---------------------------------------------------------------
__device__ __forceinline__ uint32_t smaddr(const void* p) {
    uint32_t r;
    asm("{ .reg .u64 t; cvta.to.shared.u64 t, %1; cvt.u32.u64 %0, t; }"
        : "=r"(r) : "l"(p));
    return r;
}
__device__ __forceinline__ void cpa16(uint32_t dst, const void* src) {
    asm volatile("cp.async.cg.shared.global [%0], [%1], 16;"
                 :: "r"(dst), "l"(src) : "memory");
}
__device__ __forceinline__ void ldsm4(uint32_t* r, uint32_t addr) {
    asm volatile("ldmatrix.sync.aligned.m8n8.x4.shared.b16 {%0,%1,%2,%3}, [%4];"
                 : "=r"(r[0]), "=r"(r[1]), "=r"(r[2]), "=r"(r[3]) : "r"(addr));
}
__device__ __forceinline__ void ldsm4t(uint32_t* r, uint32_t addr) {
    asm volatile("ldmatrix.sync.aligned.m8n8.x4.trans.shared.b16 {%0,%1,%2,%3}, [%4];"
                 : "=r"(r[0]), "=r"(r[1]), "=r"(r[2]), "=r"(r[3]) : "r"(addr));
}
__device__ __forceinline__ void mma_bf16(float* d, const uint32_t* a,
                                         uint32_t b0, uint32_t b1) {
    asm volatile(
        "mma.sync.aligned.m16n8k16.row.col.f32.bf16.bf16.f32 "
        "{%0,%1,%2,%3}, {%4,%5,%6,%7}, {%8,%9}, {%0,%1,%2,%3};"
        : "+f"(d[0]), "+f"(d[1]), "+f"(d[2]), "+f"(d[3])
        : "r"(a[0]), "r"(a[1]), "r"(a[2]), "r"(a[3]), "r"(b0), "r"(b1));
}
__device__ __forceinline__ uint32_t packbf(float x, float y) {
    uint32_t r;
    asm("cvt.rn.bf16x2.f32 %0, %1, %2;" : "=r"(r) : "f"(y), "f"(x));
    return r;
}
__device__ __forceinline__ uint32_t ldsu16(uint32_t a) {
    uint32_t r;
    asm volatile("ld.shared.u16 %0, [%1];" : "=r"(r) : "r"(a));
    return r;
}

// ---------------------------------------------------------------------------
// Fused bf16 hi/lo split: blocks 0..4095 -> x, then 1024 per weight.
// ---------------------------------------------------------------------------
__global__ void split_all(const float* __restrict__ x,
                          const float* __restrict__ Wq,
                          const float* __restrict__ Wk,
                          const float* __restrict__ Wv,
                          const float* __restrict__ Wo)
{
    const int bid = blockIdx.x;
    const float* s;
    __nv_bfloat16 *h, *l;
    int base;
    if (bid < 4096) { s = x; h = g_xh; l = g_xl; base = bid; }
    else {
        const int w  = (bid - 4096) >> 10;
        base = (bid - 4096) & 1023;
        s = (w == 0) ? Wq : (w == 1) ? Wk : (w == 2) ? Wv : Wo;
        h = g_wh[w]; l = g_wl[w];
    }
    const int i = (base * 256 + threadIdx.x) << 2;
    float4 v = *(const float4*)(s + i);
    __nv_bfloat16 h0 = __float2bfloat16(v.x);
    __nv_bfloat16 h1 = __float2bfloat16(v.y);
    __nv_bfloat16 h2 = __float2bfloat16(v.z);
    __nv_bfloat16 h3 = __float2bfloat16(v.w);
    __nv_bfloat162 ph0; ph0.x = h0; ph0.y = h1;
    __nv_bfloat162 ph1; ph1.x = h2; ph1.y = h3;
    __nv_bfloat162 pl0;
    pl0.x = __float2bfloat16(v.x - __bfloat162float(h0));
    pl0.y = __float2bfloat16(v.y - __bfloat162float(h1));
    __nv_bfloat162 pl1;
    pl1.x = __float2bfloat16(v.z - __bfloat162float(h2));
    pl1.y = __float2bfloat16(v.w - __bfloat162float(h3));
    *(__nv_bfloat162*)(h + i)     = ph0;
    *(__nv_bfloat162*)(h + i + 2) = ph1;
    *(__nv_bfloat162*)(l + i)     = pl0;
    *(__nv_bfloat162*)(l + i + 2) = pl1;
}

// ---------------------------------------------------------------------------
// HMMA GEMM, K-chunk 32, 2 CTAs/SM, term-pass-ordered MMAs.
// mode 0/1/2: write Q/K/V bf16 hi/lo head-transposed (Q pre-scaled 0.125).
// mode 3:     A = attention-output split, write Cp fp32 row-major.
// Row stride 80 B (= 5*16: aligned; banks 20r mod 32 cover all 32 banks
// per 8-row ldmatrix phase -> conflict-free).
// ---------------------------------------------------------------------------
#define OPB   10240                       // 128 rows * 80 B
#define STG   (4 * OPB)                   // Ah, Al, Bh, Bl = 40960
#define GEMM_SMEM (2 * STG)               // 81920

__global__ __launch_bounds__(256, 2)
void gemm_hmma(const float* __restrict__ bias, float* __restrict__ Cp, int mode)
{
    extern __shared__ char smraw[];
    const uint32_t sb = smaddr(smraw);

    const int tid  = threadIdx.x;
    const int wid  = tid >> 5;
    const int lane = tid & 31;
    const int n0   = blockIdx.x << 7;
    const int m0   = blockIdx.y << 7;

    const int widx = (mode == 3) ? 3 : mode;
    const __nv_bfloat16* Ah = (mode == 3) ? g_ah : g_xh;
    const __nv_bfloat16* Al = (mode == 3) ? g_al : g_xl;
    const __nv_bfloat16* Bh = g_wh[widx];
    const __nv_bfloat16* Bl = g_wl[widx];

    float acc[2][8][4];
#pragma unroll
    for (int mi = 0; mi < 2; mi++)
#pragma unroll
        for (int nj = 0; nj < 8; nj++)
#pragma unroll
            for (int e = 0; e < 4; e++) acc[mi][nj][e] = 0.f;

    const int lr = tid >> 2;      // 0..63
    const int lu = tid & 3;       // 16B unit within 64B row

    const int wm  = wid & 3;
    const int wn  = wid >> 2;
    const int rl  = lane & 7;
    const int seg = lane >> 3;
    const uint32_t a_off =
        (uint32_t)((wm * 32 + rl + (seg & 1) * 8) * 80 + (seg >> 1) * 16);
    const uint32_t b_off =
        (uint32_t)((wn * 64 + rl + (seg & 1) * 8) * 80 + (seg >> 1) * 16);

    // prologue: stage 0 <- chunk 0
    {
        const uint32_t stg = sb;
#pragma unroll
        for (int i = 0; i < 2; i++) {
            const int r = lr + 64 * i;
            const uint32_t dofs = (uint32_t)(r * 80 + lu * 16);
            cpa16(stg + 0 * OPB + dofs, Ah + (size_t)(m0 + r) * DIM + lu * 8);
            cpa16(stg + 1 * OPB + dofs, Al + (size_t)(m0 + r) * DIM + lu * 8);
            cpa16(stg + 2 * OPB + dofs, Bh + (size_t)(n0 + r) * DIM + lu * 8);
            cpa16(stg + 3 * OPB + dofs, Bl + (size_t)(n0 + r) * DIM + lu * 8);
        }
        asm volatile("cp.async.commit_group;" ::: "memory");
    }

    for (int c = 0; c < 32; c++) {
        if (c + 1 < 32) {
            const uint32_t stg = sb + (uint32_t)((c + 1) & 1) * STG;
            const int k0 = (c + 1) << 5;
#pragma unroll
            for (int i = 0; i < 2; i++) {
                const int r = lr + 64 * i;
                const uint32_t dofs = (uint32_t)(r * 80 + lu * 16);
                cpa16(stg + 0 * OPB + dofs, Ah + (size_t)(m0 + r) * DIM + k0 + lu * 8);
                cpa16(stg + 1 * OPB + dofs, Al + (size_t)(m0 + r) * DIM + k0 + lu * 8);
                cpa16(stg + 2 * OPB + dofs, Bh + (size_t)(n0 + r) * DIM + k0 + lu * 8);
                cpa16(stg + 3 * OPB + dofs, Bl + (size_t)(n0 + r) * DIM + k0 + lu * 8);
            }
            asm volatile("cp.async.commit_group;" ::: "memory");
            asm volatile("cp.async.wait_group 1;" ::: "memory");
        } else {
            asm volatile("cp.async.wait_group 0;" ::: "memory");
        }
        __syncthreads();

        const uint32_t stg = sb + (uint32_t)(c & 1) * STG;
#pragma unroll
        for (int ks = 0; ks < 2; ks++) {
            // load ALL fragments for this k16 step first
            uint32_t fah[2][4], fal[2][4];
#pragma unroll
            for (int mi = 0; mi < 2; mi++) {
                ldsm4(fah[mi], stg + 0 * OPB + a_off + mi * 1280 + ks * 32);
                ldsm4(fal[mi], stg + 1 * OPB + a_off + mi * 1280 + ks * 32);
            }
            uint32_t bh4[4][4], bl4[4][4];
#pragma unroll
            for (int bj = 0; bj < 4; bj++) {
                ldsm4(bh4[bj], stg + 2 * OPB + b_off + bj * 1280 + ks * 32);
                ldsm4(bl4[bj], stg + 3 * OPB + b_off + bj * 1280 + ks * 32);
            }
            // pass 1: Ah*Bh  (16 MMAs; each acc touched once)
#pragma unroll
            for (int bj = 0; bj < 4; bj++)
#pragma unroll
                for (int mi = 0; mi < 2; mi++) {
                    mma_bf16(acc[mi][2 * bj + 0], fah[mi], bh4[bj][0], bh4[bj][2]);
                    mma_bf16(acc[mi][2 * bj + 1], fah[mi], bh4[bj][1], bh4[bj][3]);
                }
            // pass 2: Ah*Bl
#pragma unroll
            for (int bj = 0; bj < 4; bj++)
#pragma unroll
                for (int mi = 0; mi < 2; mi++) {
                    mma_bf16(acc[mi][2 * bj + 0], fah[mi], bl4[bj][0], bl4[bj][2]);
                    mma_bf16(acc[mi][2 * bj + 1], fah[mi], bl4[bj][1], bl4[bj][3]);
                }
            // pass 3: Al*Bh
#pragma unroll
            for (int bj = 0; bj < 4; bj++)
#pragma unroll
                for (int mi = 0; mi < 2; mi++) {
                    mma_bf16(acc[mi][2 * bj + 0], fal[mi], bh4[bj][0], bh4[bj][2]);
                    mma_bf16(acc[mi][2 * bj + 1], fal[mi], bh4[bj][1], bh4[bj][3]);
                }
        }
        __syncthreads();
    }

    // ---- epilogue ----
    const int qrow = lane >> 2;
    const int qcol = (lane & 3) << 1;
    const float qscale = (mode == 0) ? 0.125f : 1.0f;
    __nv_bfloat16* Gh = (mode == 0) ? g_Qh : (mode == 1) ? g_Kh : g_Vh;
    __nv_bfloat16* Gl = (mode == 0) ? g_Ql : (mode == 1) ? g_Kl : g_Vl;
#pragma unroll
    for (int mi = 0; mi < 2; mi++) {
#pragma unroll
        for (int nj = 0; nj < 8; nj++) {
            const int col = n0 + wn * 64 + nj * 8 + qcol;
            const float2 bv = *(const float2*)&bias[col];
            const int mrow = m0 + wm * 32 + mi * 16 + qrow;
#pragma unroll
            for (int half = 0; half < 2; half++) {
                const int m = mrow + half * 8;
                float ox = acc[mi][nj][2 * half + 0] + bv.x;
                float oy = acc[mi][nj][2 * half + 1] + bv.y;
                if (mode == 3) {
                    float2 o; o.x = ox; o.y = oy;
                    *(float2*)&Cp[(size_t)m * DIM + col] = o;
                } else {
                    ox *= qscale; oy *= qscale;
                    const int h    = col >> 6;
                    const int dh   = col & 63;
                    const int bidx = m >> 11;
                    const int nn   = m & (SEQ - 1);
                    const size_t base =
                        ((size_t)(bidx * HEADS + h) * SEQ + nn) * HDIM + dh;
                    __nv_bfloat16 hx = __float2bfloat16(ox);
                    __nv_bfloat16 hy = __float2bfloat16(oy);
                    __nv_bfloat162 ph; ph.x = hx; ph.y = hy;
                    __nv_bfloat162 pl;
                    pl.x = __float2bfloat16(ox - __bfloat162float(hx));
                    pl.y = __float2bfloat16(oy - __bfloat162float(hy));
                    *(__nv_bfloat162*)&Gh[base] = ph;
                    *(__nv_bfloat162*)&Gl[base] = pl;
                }
            }
        }
    }
}

// ---------------------------------------------------------------------------
// HMMA flash attention (R13, unchanged). CTA = (b, h, 64-q-tile), 128 thr,
// 3 CTAs/SM. Q staged through the kt=1 buffer; epilogue writes g_ah/g_al.
// ---------------------------------------------------------------------------
#define AKH      0
#define AKL      9216
#define AVH      18432
#define AVL      27648
#define AMSK     36864
#define ASTAGE   37120
#define ATTN_SMEM (2 * ASTAGE)            // 74240

__global__ __launch_bounds__(128, 3)
void attn_hmma(const unsigned char* __restrict__ mask)
{
    extern __shared__ char smraw[];
    const uint32_t sb = smaddr(smraw);

    const int qt  = blockIdx.x;
    const int h   = blockIdx.y;
    const int b   = blockIdx.z;
    const int tid = threadIdx.x;
    const int wid = tid >> 5;
    const int lane = tid & 31;
    const int rl  = lane & 7;
    const int seg = lane >> 3;

    const size_t bh = (size_t)(b * HEADS + h) * SEQ * HDIM;
    const unsigned char* mg = mask + b * SEQ;

    const int lu = tid & 7;
    const int lr = tid >> 3;

    const uint32_t st0 = sb;
    const uint32_t st1 = sb + ASTAGE;

    // ---- prologue: Q (hi/lo) -> stage1 K area; chunk 0 K/V -> stage0 ----
    {
        const int qb = qt << 6;
#pragma unroll
        for (int i = 0; i < 4; i++) {
            const int r = lr + 16 * i;
            const uint32_t dofs = (uint32_t)(r * 144 + lu * 16);
            cpa16(st1 + AKH + dofs, g_Qh + bh + (size_t)(qb + r) * HDIM + lu * 8);
            cpa16(st1 + AKL + dofs, g_Ql + bh + (size_t)(qb + r) * HDIM + lu * 8);
            cpa16(st0 + AKH + dofs, g_Kh + bh + (size_t)r * HDIM + lu * 8);
            cpa16(st0 + AKL + dofs, g_Kl + bh + (size_t)r * HDIM + lu * 8);
            cpa16(st0 + AVH + dofs, g_Vh + bh + (size_t)r * HDIM + lu * 8);
            cpa16(st0 + AVL + dofs, g_Vl + bh + (size_t)r * HDIM + lu * 8);
        }
        if (tid < 4) cpa16(st0 + AMSK + tid * 16, mg + tid * 16);
        asm volatile("cp.async.commit_group;" ::: "memory");
        asm volatile("cp.async.wait_group 0;" ::: "memory");
        __syncthreads();
    }

    // ---- Q fragments (register-resident), then release stage1 ----
    uint32_t qh[4][4], ql[4][4];
    {
        const uint32_t qa = st1 +
            (uint32_t)((wid * 16 + rl + (seg & 1) * 8) * 144 + (seg >> 1) * 16);
#pragma unroll
        for (int ks = 0; ks < 4; ks++) {
            ldsm4(qh[ks], qa + AKH + ks * 32);
            ldsm4(ql[ks], qa + AKL + ks * 32);
        }
    }
    __syncthreads();

    float oacc[8][4];
#pragma unroll
    for (int nf = 0; nf < 8; nf++)
#pragma unroll
        for (int e = 0; e < 4; e++) oacc[nf][e] = 0.f;
    float mr0 = -1e30f, mr1 = -1e30f, lr0 = 0.f, lr1 = 0.f;

    const uint32_t kfo = (uint32_t)((rl + (seg & 1) * 8) * 144 + (seg >> 1) * 16);
    const uint32_t vfo = kfo;

    for (int kt = 0; kt < SEQ / 64; kt++) {
        const uint32_t stg = sb + (uint32_t)(kt & 1) * ASTAGE;

        if (kt + 1 < SEQ / 64) {
            const uint32_t stn = sb + (uint32_t)((kt + 1) & 1) * ASTAGE;
            const int kb = (kt + 1) << 6;
#pragma unroll
            for (int i = 0; i < 4; i++) {
                const int r = lr + 16 * i;
                const uint32_t dofs = (uint32_t)(r * 144 + lu * 16);
                cpa16(stn + AKH + dofs, g_Kh + bh + (size_t)(kb + r) * HDIM + lu * 8);
                cpa16(stn + AKL + dofs, g_Kl + bh + (size_t)(kb + r) * HDIM + lu * 8);
                cpa16(stn + AVH + dofs, g_Vh + bh + (size_t)(kb + r) * HDIM + lu * 8);
                cpa16(stn + AVL + dofs, g_Vl + bh + (size_t)(kb + r) * HDIM + lu * 8);
            }
            if (tid < 4) cpa16(stn + AMSK + tid * 16, mg + kb + tid * 16);
            asm volatile("cp.async.commit_group;" ::: "memory");
        }

        // ---- S = Q K^T (hi/lo split) ----
        float sacc[8][4];
#pragma unroll
        for (int nf = 0; nf < 8; nf++)
#pragma unroll
            for (int e = 0; e < 4; e++) sacc[nf][e] = 0.f;

#pragma unroll
        for (int ks = 0; ks < 4; ks++) {
#pragma unroll
            for (int np = 0; np < 4; np++) {
                const uint32_t ka = stg + (uint32_t)(np * 16 * 144 + ks * 32) + kfo;
                uint32_t bh4[4], bl4[4];
                ldsm4(bh4, ka + AKH);
                ldsm4(bl4, ka + AKL);
                const int j0 = 2 * np, j1 = 2 * np + 1;
                mma_bf16(sacc[j0], qh[ks], bh4[0], bh4[2]);
                mma_bf16(sacc[j1], qh[ks], bh4[1], bh4[3]);
                mma_bf16(sacc[j0], qh[ks], bl4[0], bl4[2]);
                mma_bf16(sacc[j1], qh[ks], bl4[1], bl4[3]);
                mma_bf16(sacc[j0], ql[ks], bh4[0], bh4[2]);
                mma_bf16(sacc[j1], ql[ks], bh4[1], bh4[3]);
            }
        }

        // ---- mask + online softmax ----
        float mx0 = -1e30f, mx1 = -1e30f;
#pragma unroll
        for (int nf = 0; nf < 8; nf++) {
            const uint32_t mm = ldsu16(stg + AMSK + (uint32_t)(nf * 8 + 2 * (lane & 3)));
            if (mm & 0x00FFu)  { sacc[nf][0] = -20000.f; sacc[nf][2] = -20000.f; }
            if (mm & 0xFF00u)  { sacc[nf][1] = -20000.f; sacc[nf][3] = -20000.f; }
            mx0 = fmaxf(mx0, fmaxf(sacc[nf][0], sacc[nf][1]));
            mx1 = fmaxf(mx1, fmaxf(sacc[nf][2], sacc[nf][3]));
        }
        mx0 = fmaxf(mx0, __shfl_xor_sync(0xffffffffu, mx0, 1));
        mx0 = fmaxf(mx0, __shfl_xor_sync(0xffffffffu, mx0, 2));
        mx1 = fmaxf(mx1, __shfl_xor_sync(0xffffffffu, mx1, 1));
        mx1 = fmaxf(mx1, __shfl_xor_sync(0xffffffffu, mx1, 2));
        const float mn0 = fmaxf(mr0, mx0);
        const float mn1 = fmaxf(mr1, mx1);
        const float a0 = __expf(mr0 - mn0);
        const float a1 = __expf(mr1 - mn1);
        float ls0 = 0.f, ls1 = 0.f;
#pragma unroll
        for (int nf = 0; nf < 8; nf++) {
            sacc[nf][0] = __expf(sacc[nf][0] - mn0);
            sacc[nf][1] = __expf(sacc[nf][1] - mn0);
            sacc[nf][2] = __expf(sacc[nf][2] - mn1);
            sacc[nf][3] = __expf(sacc[nf][3] - mn1);
            ls0 += sacc[nf][0] + sacc[nf][1];
            ls1 += sacc[nf][2] + sacc[nf][3];
        }
        lr0 = lr0 * a0 + ls0;
        lr1 = lr1 * a1 + ls1;
        mr0 = mn0; mr1 = mn1;
#pragma unroll
        for (int nf = 0; nf < 8; nf++) {
            oacc[nf][0] *= a0; oacc[nf][1] *= a0;
            oacc[nf][2] *= a1; oacc[nf][3] *= a1;
        }

        // ---- O += P V (P split in-register) ----
#pragma unroll
        for (int ks = 0; ks < 4; ks++) {
            const float* f0 = sacc[2 * ks];
            const float* f1 = sacc[2 * ks + 1];
            uint32_t ah4[4], al4[4];
#pragma unroll
            for (int e = 0; e < 4; e++) {
                const float px = (e < 2) ? f0[2 * e]     : f1[2 * (e - 2)];
                const float py = (e < 2) ? f0[2 * e + 1] : f1[2 * (e - 2) + 1];
                const __nv_bfloat16 hx = __float2bfloat16(px);
                const __nv_bfloat16 hy = __float2bfloat16(py);
                __nv_bfloat162 pp; pp.x = hx; pp.y = hy;
                ah4[e] = *(const uint32_t*)&pp;
                al4[e] = packbf(px - __bfloat162float(hx),
                                py - __bfloat162float(hy));
            }
#pragma unroll
            for (int np = 0; np < 4; np++) {
                const uint32_t va = stg + (uint32_t)(ks * 16 * 144 + np * 32) + vfo;
                uint32_t vh4[4], vl4[4];
                ldsm4t(vh4, va + AVH);
                ldsm4t(vl4, va + AVL);
                const int j0 = 2 * np, j1 = 2 * np + 1;
                mma_bf16(oacc[j0], ah4, vh4[0], vh4[1]);
                mma_bf16(oacc[j1], ah4, vh4[2], vh4[3]);
                mma_bf16(oacc[j0], ah4, vl4[0], vl4[1]);
                mma_bf16(oacc[j1], ah4, vl4[2], vl4[3]);
                mma_bf16(oacc[j0], al4, vh4[0], vh4[1]);
                mma_bf16(oacc[j1], al4, vh4[2], vh4[3]);
            }
        }

        if (kt + 1 < SEQ / 64)
            asm volatile("cp.async.wait_group 0;" ::: "memory");
        __syncthreads();
    }

    // ---- finalize: quartet l-reduce, normalize, write hi/lo split ----
    float l0 = lr0, l1 = lr1;
    l0 += __shfl_xor_sync(0xffffffffu, l0, 1);
    l0 += __shfl_xor_sync(0xffffffffu, l0, 2);
    l1 += __shfl_xor_sync(0xffffffffu, l1, 1);
    l1 += __shfl_xor_sync(0xffffffffu, l1, 2);
    const float i0 = 1.f / l0, i1 = 1.f / l1;

    const int r0 = qt * 64 + wid * 16 + (lane >> 2);
    const int r1 = r0 + 8;
    const int cb = h * 64 + 2 * (lane & 3);
    const size_t o0 = (size_t)(b * SEQ + r0) * DIM + cb;
    const size_t o1 = (size_t)(b * SEQ + r1) * DIM + cb;
#pragma unroll
    for (int nf = 0; nf < 8; nf++) {
        const float v0x = oacc[nf][0] * i0, v0y = oacc[nf][1] * i0;
        const float v1x = oacc[nf][2] * i1, v1y = oacc[nf][3] * i1;
        __nv_bfloat16 h0x = __float2bfloat16(v0x), h0y = __float2bfloat16(v0y);
        __nv_bfloat16 h1x = __float2bfloat16(v1x), h1y = __float2bfloat16(v1y);
        __nv_bfloat162 p0h; p0h.x = h0x; p0h.y = h0y;
        __nv_bfloat162 p1h; p1h.x = h1x; p1h.y = h1y;
        __nv_bfloat162 p0l;
        p0l.x = __float2bfloat16(v0x - __bfloat162float(h0x));
        p0l.y = __float2bfloat16(v0y - __bfloat162float(h0y));
        __nv_bfloat162 p1l;
        p1l.x = __float2bfloat16(v1x - __bfloat162float(h1x));
        p1l.y = __float2bfloat16(v1y - __bfloat162float(h1y));
        *(__nv_bfloat162*)&g_ah[o0 + nf * 8] = p0h;
        *(__nv_bfloat162*)&g_al[o0 + nf * 8] = p0l;
        *(__nv_bfloat162*)&g_ah[o1 + nf * 8] = p1h;
        *(__nv_bfloat162*)&g_al[o1 + nf * 8] = p1l;
    }
}

// ---------------------------------------------------------------------------
extern "C" void kernel_launch(void* const* d_in, const int* in_sizes, int n_in,
                              void* d_out, int out_size)
{
    const float* x          = (const float*)d_in[0];
    const unsigned char* mk = (const unsigned char*)d_in[1];
    const float* Wq = (const float*)d_in[2];
    const float* bq = (const float*)d_in[3];
    const float* Wk = (const float*)d_in[4];
    const float* bk = (const float*)d_in[5];
    const float* Wv = (const float*)d_in[6];
    const float* bv = (const float*)d_in[7];
    const float* Wo = (const float*)d_in[8];
    const float* bo = (const float*)d_in[9];
    float* out = (float*)d_out;

    cudaFuncSetAttribute(gemm_hmma, cudaFuncAttributeMaxDynamicSharedMemorySize,
                         GEMM_SMEM);
    cudaFuncSetAttribute(attn_hmma, cudaFuncAttributeMaxDynamicSharedMemorySize,
                         ATTN_SMEM);

    split_all<<<8192, 256>>>(x, Wq, Wk, Wv, Wo);

    dim3 gg(DIM / 128, MROWS / 128);   // (8, 32)
    gemm_hmma<<<gg, 256, GEMM_SMEM>>>(bq, out, 0);
    gemm_hmma<<<gg, 256, GEMM_SMEM>>>(bk, out, 1);
    gemm_hmma<<<gg, 256, GEMM_SMEM>>>(bv, out, 2);

    attn_hmma<<<dim3(SEQ / 64, HEADS, BATCH), 128, ATTN_SMEM>>>(mk);

    gemm_hmma<<<gg, 256, GEMM_SMEM>>>(bo, out, 3);
}

// round 17
// speedup vs baseline: 8.0306x; 2.4860x over previous
#include <cuda_runtime.h>
#include <cuda_fp16.h>
#include <cstdint>

// ---------------------------------------------------------------------------
// MultiheadSelfAttention: B=2, N=2048, D=1024, H=16, hd=64, fp32.
// R16: single-product fp16 HMMA everywhere (no hi/lo split). The mma.sync
// path saturates at ~1024 FLOP/cyc/SM; the 3x bf16-split work was the cost.
// fp16's 11 mantissa bits predict rel_err ~3-7e-4 < 1e-3.
//  - GEMM: K-chunk 64, smem 72KB, 2 CTAs/SM, double-buffered cp.async.
//  - Attention: fp16 S=QK^T and O=PV, 4 CTAs/SM.
//  - Attention epilogue writes fp16 A directly for the output projection.
// ---------------------------------------------------------------------------

#define BATCH   2
#define SEQ     2048
#define DIM     1024
#define HEADS   16
#define HDIM    64
#define MROWS   (BATCH * SEQ)            // 4096

// fp16 operands
__device__ __half g_x16[MROWS * DIM];
__device__ __half g_w16[4][DIM * DIM];
__device__ __half g_a16[MROWS * DIM];
#define QKVN (BATCH * HEADS * SEQ * HDIM)
__device__ __half g_Q16[QKVN], g_K16[QKVN], g_V16[QKVN];

typedef unsigned long long u64;

// ---- helpers ---------------------------------------------------------------
__device__ __forceinline__ uint32_t smaddr(const void* p) {
    uint32_t r;
    asm("{ .reg .u64 t; cvta.to.shared.u64 t, %1; cvt.u32.u64 %0, t; }"
        : "=r"(r) : "l"(p));
    return r;
}
__device__ __forceinline__ void cpa16(uint32_t dst, const void* src) {
    asm volatile("cp.async.cg.shared.global [%0], [%1], 16;"
                 :: "r"(dst), "l"(src) : "memory");
}
__device__ __forceinline__ void ldsm4(uint32_t* r, uint32_t addr) {
    asm volatile("ldmatrix.sync.aligned.m8n8.x4.shared.b16 {%0,%1,%2,%3}, [%4];"
                 : "=r"(r[0]), "=r"(r[1]), "=r"(r[2]), "=r"(r[3]) : "r"(addr));
}
__device__ __forceinline__ void ldsm4t(uint32_t* r, uint32_t addr) {
    asm volatile("ldmatrix.sync.aligned.m8n8.x4.trans.shared.b16 {%0,%1,%2,%3}, [%4];"
                 : "=r"(r[0]), "=r"(r[1]), "=r"(r[2]), "=r"(r[3]) : "r"(addr));
}
__device__ __forceinline__ void mma_f16(float* d, const uint32_t* a,
                                        uint32_t b0, uint32_t b1) {
    asm volatile(
        "mma.sync.aligned.m16n8k16.row.col.f32.f16.f16.f32 "
        "{%0,%1,%2,%3}, {%4,%5,%6,%7}, {%8,%9}, {%0,%1,%2,%3};"
        : "+f"(d[0]), "+f"(d[1]), "+f"(d[2]), "+f"(d[3])
        : "r"(a[0]), "r"(a[1]), "r"(a[2]), "r"(a[3]), "r"(b0), "r"(b1));
}
__device__ __forceinline__ uint32_t ldsu16(uint32_t a) {
    uint32_t r;
    asm volatile("ld.shared.u16 %0, [%1];" : "=r"(r) : "r"(a));
    return r;
}
__device__ __forceinline__ uint32_t packh2(float x, float y) {
    __half2 h = __floats2half2_rn(x, y);
    return *(const uint32_t*)&h;
}

// ---------------------------------------------------------------------------
// fp16 convert pre-pass: blocks 0..4095 -> x, then 1024 per weight.
// ---------------------------------------------------------------------------
__global__ void conv16(const float* __restrict__ x,
                       const float* __restrict__ Wq,
                       const float* __restrict__ Wk,
                       const float* __restrict__ Wv,
                       const float* __restrict__ Wo)
{
    const int bid = blockIdx.x;
    const float* s;
    __half* h;
    int base;
    if (bid < 4096) { s = x; h = g_x16; base = bid; }
    else {
        const int w  = (bid - 4096) >> 10;
        base = (bid - 4096) & 1023;
        s = (w == 0) ? Wq : (w == 1) ? Wk : (w == 2) ? Wv : Wo;
        h = g_w16[w];
    }
    const int i = (base * 256 + threadIdx.x) << 2;
    float4 v = *(const float4*)(s + i);
    __half2 p0 = __floats2half2_rn(v.x, v.y);
    __half2 p1 = __floats2half2_rn(v.z, v.w);
    *(__half2*)(h + i)     = p0;
    *(__half2*)(h + i + 2) = p1;
}

// ---------------------------------------------------------------------------
// fp16 HMMA GEMM: C[m][n] = sum_k A[m][k]*B[n][k] + bias[n].
// CTA tile 128x128, K-chunk 64, 2 CTAs/SM, double-buffered cp.async.
// Row stride 144 B (9*16: aligned, conflict-free ldmatrix — proven in R6).
// mode 0/1/2: write Q/K/V fp16 head-transposed (Q pre-scaled 0.125).
// mode 3:     A = g_a16, write Cp fp32 row-major.
// ---------------------------------------------------------------------------
#define OPB   18432                       // 128 rows * 144 B
#define STG   (2 * OPB)                   // A, B = 36864
#define GEMM_SMEM (2 * STG)               // 73728

__global__ __launch_bounds__(256, 2)
void gemm_hmma(const float* __restrict__ bias, float* __restrict__ Cp, int mode)
{
    extern __shared__ char smraw[];
    const uint32_t sb = smaddr(smraw);

    const int tid  = threadIdx.x;
    const int wid  = tid >> 5;
    const int lane = tid & 31;
    const int n0   = blockIdx.x << 7;
    const int m0   = blockIdx.y << 7;

    const int widx = (mode == 3) ? 3 : mode;
    const __half* A = (mode == 3) ? g_a16 : g_x16;
    const __half* B = g_w16[widx];

    float acc[2][8][4];
#pragma unroll
    for (int mi = 0; mi < 2; mi++)
#pragma unroll
        for (int nj = 0; nj < 8; nj++)
#pragma unroll
            for (int e = 0; e < 4; e++) acc[mi][nj][e] = 0.f;

    const int lr = tid >> 3;      // 0..31
    const int lu = tid & 7;       // 16B unit within 128B row

    const int wm  = wid & 3;
    const int wn  = wid >> 2;
    const int rl  = lane & 7;
    const int seg = lane >> 3;
    const uint32_t a_off =
        (uint32_t)((wm * 32 + rl + (seg & 1) * 8) * 144 + (seg >> 1) * 16);
    const uint32_t b_off =
        (uint32_t)((wn * 64 + rl + (seg & 1) * 8) * 144 + (seg >> 1) * 16);

    // prologue: stage 0 <- chunk 0
    {
        const uint32_t stg = sb;
#pragma unroll
        for (int i = 0; i < 4; i++) {
            const int r = lr + 32 * i;
            const uint32_t dofs = (uint32_t)(r * 144 + lu * 16);
            cpa16(stg + 0 * OPB + dofs, A + (size_t)(m0 + r) * DIM + lu * 8);
            cpa16(stg + 1 * OPB + dofs, B + (size_t)(n0 + r) * DIM + lu * 8);
        }
        asm volatile("cp.async.commit_group;" ::: "memory");
    }

    for (int c = 0; c < 16; c++) {
        if (c + 1 < 16) {
            const uint32_t stg = sb + (uint32_t)((c + 1) & 1) * STG;
            const int k0 = (c + 1) << 6;
#pragma unroll
            for (int i = 0; i < 4; i++) {
                const int r = lr + 32 * i;
                const uint32_t dofs = (uint32_t)(r * 144 + lu * 16);
                cpa16(stg + 0 * OPB + dofs, A + (size_t)(m0 + r) * DIM + k0 + lu * 8);
                cpa16(stg + 1 * OPB + dofs, B + (size_t)(n0 + r) * DIM + k0 + lu * 8);
            }
            asm volatile("cp.async.commit_group;" ::: "memory");
            asm volatile("cp.async.wait_group 1;" ::: "memory");
        } else {
            asm volatile("cp.async.wait_group 0;" ::: "memory");
        }
        __syncthreads();

        const uint32_t stg = sb + (uint32_t)(c & 1) * STG;
#pragma unroll
        for (int ks = 0; ks < 4; ks++) {
            uint32_t fa[2][4];
#pragma unroll
            for (int mi = 0; mi < 2; mi++)
                ldsm4(fa[mi], stg + 0 * OPB + a_off + mi * 2304 + ks * 32);
            uint32_t fb[4][4];
#pragma unroll
            for (int bj = 0; bj < 4; bj++)
                ldsm4(fb[bj], stg + 1 * OPB + b_off + bj * 2304 + ks * 32);
#pragma unroll
            for (int bj = 0; bj < 4; bj++)
#pragma unroll
                for (int mi = 0; mi < 2; mi++) {
                    mma_f16(acc[mi][2 * bj + 0], fa[mi], fb[bj][0], fb[bj][2]);
                    mma_f16(acc[mi][2 * bj + 1], fa[mi], fb[bj][1], fb[bj][3]);
                }
        }
        __syncthreads();
    }

    // ---- epilogue ----
    const int qrow = lane >> 2;
    const int qcol = (lane & 3) << 1;
    const float qscale = (mode == 0) ? 0.125f : 1.0f;
    __half* G = (mode == 0) ? g_Q16 : (mode == 1) ? g_K16 : g_V16;
#pragma unroll
    for (int mi = 0; mi < 2; mi++) {
#pragma unroll
        for (int nj = 0; nj < 8; nj++) {
            const int col = n0 + wn * 64 + nj * 8 + qcol;
            const float2 bv = *(const float2*)&bias[col];
            const int mrow = m0 + wm * 32 + mi * 16 + qrow;
#pragma unroll
            for (int half = 0; half < 2; half++) {
                const int m = mrow + half * 8;
                float ox = acc[mi][nj][2 * half + 0] + bv.x;
                float oy = acc[mi][nj][2 * half + 1] + bv.y;
                if (mode == 3) {
                    float2 o; o.x = ox; o.y = oy;
                    *(float2*)&Cp[(size_t)m * DIM + col] = o;
                } else {
                    const int h    = col >> 6;
                    const int dh   = col & 63;
                    const int bidx = m >> 11;
                    const int nn   = m & (SEQ - 1);
                    const size_t base =
                        ((size_t)(bidx * HEADS + h) * SEQ + nn) * HDIM + dh;
                    *(__half2*)&G[base] =
                        __floats2half2_rn(ox * qscale, oy * qscale);
                }
            }
        }
    }
}

// ---------------------------------------------------------------------------
// fp16 HMMA flash attention. CTA = (b, h, 64-q-tile), 128 threads, 4 CTAs/SM.
// Q staged through the kt=1 K buffer; epilogue writes g_a16 directly.
// ---------------------------------------------------------------------------
#define AK       0
#define AV       9216
#define AMSK     18432
#define ASTAGE   18560
#define ATTN_SMEM (2 * ASTAGE)            // 37120

__global__ __launch_bounds__(128, 4)
void attn_hmma(const unsigned char* __restrict__ mask)
{
    extern __shared__ char smraw[];
    const uint32_t sb = smaddr(smraw);

    const int qt  = blockIdx.x;
    const int h   = blockIdx.y;
    const int b   = blockIdx.z;
    const int tid = threadIdx.x;
    const int wid = tid >> 5;
    const int lane = tid & 31;
    const int rl  = lane & 7;
    const int seg = lane >> 3;

    const size_t bh = (size_t)(b * HEADS + h) * SEQ * HDIM;
    const unsigned char* mg = mask + b * SEQ;

    const int lu = tid & 7;          // 16B unit within 128B row
    const int lr = tid >> 3;         // row base 0..15

    const uint32_t st0 = sb;
    const uint32_t st1 = sb + ASTAGE;

    // ---- prologue: Q -> stage1 K area; chunk 0 K/V -> stage0 ----
    {
        const int qb = qt << 6;
#pragma unroll
        for (int i = 0; i < 4; i++) {
            const int r = lr + 16 * i;
            const uint32_t dofs = (uint32_t)(r * 144 + lu * 16);
            cpa16(st1 + AK + dofs, g_Q16 + bh + (size_t)(qb + r) * HDIM + lu * 8);
            cpa16(st0 + AK + dofs, g_K16 + bh + (size_t)r * HDIM + lu * 8);
            cpa16(st0 + AV + dofs, g_V16 + bh + (size_t)r * HDIM + lu * 8);
        }
        if (tid < 4) cpa16(st0 + AMSK + tid * 16, mg + tid * 16);
        asm volatile("cp.async.commit_group;" ::: "memory");
        asm volatile("cp.async.wait_group 0;" ::: "memory");
        __syncthreads();
    }

    // ---- Q fragments (register-resident), then release stage1 ----
    uint32_t qf[4][4];
    {
        const uint32_t qa = st1 + AK +
            (uint32_t)((wid * 16 + rl + (seg & 1) * 8) * 144 + (seg >> 1) * 16);
#pragma unroll
        for (int ks = 0; ks < 4; ks++)
            ldsm4(qf[ks], qa + ks * 32);
    }
    __syncthreads();   // all warps done reading Q before stage1 is overwritten

    float oacc[8][4];
#pragma unroll
    for (int nf = 0; nf < 8; nf++)
#pragma unroll
        for (int e = 0; e < 4; e++) oacc[nf][e] = 0.f;
    float mr0 = -1e30f, mr1 = -1e30f, lr0 = 0.f, lr1 = 0.f;

    const uint32_t kfo = (uint32_t)((rl + (seg & 1) * 8) * 144 + (seg >> 1) * 16);
    const uint32_t vfo = kfo;

    for (int kt = 0; kt < SEQ / 64; kt++) {
        const uint32_t stg = sb + (uint32_t)(kt & 1) * ASTAGE;

        if (kt + 1 < SEQ / 64) {
            const uint32_t stn = sb + (uint32_t)((kt + 1) & 1) * ASTAGE;
            const int kb = (kt + 1) << 6;
#pragma unroll
            for (int i = 0; i < 4; i++) {
                const int r = lr + 16 * i;
                const uint32_t dofs = (uint32_t)(r * 144 + lu * 16);
                cpa16(stn + AK + dofs, g_K16 + bh + (size_t)(kb + r) * HDIM + lu * 8);
                cpa16(stn + AV + dofs, g_V16 + bh + (size_t)(kb + r) * HDIM + lu * 8);
            }
            if (tid < 4) cpa16(stn + AMSK + tid * 16, mg + kb + tid * 16);
            asm volatile("cp.async.commit_group;" ::: "memory");
        }

        // ---- S = Q K^T ----
        float sacc[8][4];
#pragma unroll
        for (int nf = 0; nf < 8; nf++)
#pragma unroll
            for (int e = 0; e < 4; e++) sacc[nf][e] = 0.f;

#pragma unroll
        for (int ks = 0; ks < 4; ks++) {
#pragma unroll
            for (int np = 0; np < 4; np++) {
                const uint32_t ka = stg + AK
                    + (uint32_t)(np * 16 * 144 + ks * 32) + kfo;
                uint32_t kb4[4];
                ldsm4(kb4, ka);
                mma_f16(sacc[2 * np + 0], qf[ks], kb4[0], kb4[2]);
                mma_f16(sacc[2 * np + 1], qf[ks], kb4[1], kb4[3]);
            }
        }

        // ---- mask + online softmax ----
        float mx0 = -1e30f, mx1 = -1e30f;
#pragma unroll
        for (int nf = 0; nf < 8; nf++) {
            const uint32_t mm = ldsu16(stg + AMSK + (uint32_t)(nf * 8 + 2 * (lane & 3)));
            if (mm & 0x00FFu)  { sacc[nf][0] = -20000.f; sacc[nf][2] = -20000.f; }
            if (mm & 0xFF00u)  { sacc[nf][1] = -20000.f; sacc[nf][3] = -20000.f; }
            mx0 = fmaxf(mx0, fmaxf(sacc[nf][0], sacc[nf][1]));
            mx1 = fmaxf(mx1, fmaxf(sacc[nf][2], sacc[nf][3]));
        }
        mx0 = fmaxf(mx0, __shfl_xor_sync(0xffffffffu, mx0, 1));
        mx0 = fmaxf(mx0, __shfl_xor_sync(0xffffffffu, mx0, 2));
        mx1 = fmaxf(mx1, __shfl_xor_sync(0xffffffffu, mx1, 1));
        mx1 = fmaxf(mx1, __shfl_xor_sync(0xffffffffu, mx1, 2));
        const float mn0 = fmaxf(mr0, mx0);
        const float mn1 = fmaxf(mr1, mx1);
        const float a0 = __expf(mr0 - mn0);
        const float a1 = __expf(mr1 - mn1);
        float ls0 = 0.f, ls1 = 0.f;
#pragma unroll
        for (int nf = 0; nf < 8; nf++) {
            sacc[nf][0] = __expf(sacc[nf][0] - mn0);
            sacc[nf][1] = __expf(sacc[nf][1] - mn0);
            sacc[nf][2] = __expf(sacc[nf][2] - mn1);
            sacc[nf][3] = __expf(sacc[nf][3] - mn1);
            ls0 += sacc[nf][0] + sacc[nf][1];
            ls1 += sacc[nf][2] + sacc[nf][3];
        }
        lr0 = lr0 * a0 + ls0;
        lr1 = lr1 * a1 + ls1;
        mr0 = mn0; mr1 = mn1;
#pragma unroll
        for (int nf = 0; nf < 8; nf++) {
            oacc[nf][0] *= a0; oacc[nf][1] *= a0;
            oacc[nf][2] *= a1; oacc[nf][3] *= a1;
        }

        // ---- O += P V (P packed to fp16 in-register) ----
#pragma unroll
        for (int ks = 0; ks < 4; ks++) {
            const float* f0 = sacc[2 * ks];
            const float* f1 = sacc[2 * ks + 1];
            uint32_t pa[4];
            pa[0] = packh2(f0[0], f0[1]);
            pa[1] = packh2(f0[2], f0[3]);
            pa[2] = packh2(f1[0], f1[1]);
            pa[3] = packh2(f1[2], f1[3]);
#pragma unroll
            for (int np = 0; np < 4; np++) {
                const uint32_t va = stg + AV
                    + (uint32_t)(ks * 16 * 144 + np * 32) + vfo;
                uint32_t vf[4];
                ldsm4t(vf, va);
                mma_f16(oacc[2 * np + 0], pa, vf[0], vf[1]);
                mma_f16(oacc[2 * np + 1], pa, vf[2], vf[3]);
            }
        }

        if (kt + 1 < SEQ / 64)
            asm volatile("cp.async.wait_group 0;" ::: "memory");
        __syncthreads();
    }

    // ---- finalize: quartet l-reduce, normalize, write fp16 A ----
    float l0 = lr0, l1 = lr1;
    l0 += __shfl_xor_sync(0xffffffffu, l0, 1);
    l0 += __shfl_xor_sync(0xffffffffu, l0, 2);
    l1 += __shfl_xor_sync(0xffffffffu, l1, 1);
    l1 += __shfl_xor_sync(0xffffffffu, l1, 2);
    const float i0 = 1.f / l0, i1 = 1.f / l1;

    const int r0 = qt * 64 + wid * 16 + (lane >> 2);
    const int r1 = r0 + 8;
    const int cb = h * 64 + 2 * (lane & 3);
    const size_t o0 = (size_t)(b * SEQ + r0) * DIM + cb;
    const size_t o1 = (size_t)(b * SEQ + r1) * DIM + cb;
#pragma unroll
    for (int nf = 0; nf < 8; nf++) {
        *(__half2*)&g_a16[o0 + nf * 8] =
            __floats2half2_rn(oacc[nf][0] * i0, oacc[nf][1] * i0);
        *(__half2*)&g_a16[o1 + nf * 8] =
            __floats2half2_rn(oacc[nf][2] * i1, oacc[nf][3] * i1);
    }
}

// ---------------------------------------------------------------------------
extern "C" void kernel_launch(void* const* d_in, const int* in_sizes, int n_in,
                              void* d_out, int out_size)
{
    const float* x          = (const float*)d_in[0];
    const unsigned char* mk = (const unsigned char*)d_in[1];
    const float* Wq = (const float*)d_in[2];
    const float* bq = (const float*)d_in[3];
    const float* Wk = (const float*)d_in[4];
    const float* bk = (const float*)d_in[5];
    const float* Wv = (const float*)d_in[6];
    const float* bv = (const float*)d_in[7];
    const float* Wo = (const float*)d_in[8];
    const float* bo = (const float*)d_in[9];
    float* out = (float*)d_out;

    cudaFuncSetAttribute(gemm_hmma, cudaFuncAttributeMaxDynamicSharedMemorySize,
                         GEMM_SMEM);
    cudaFuncSetAttribute(attn_hmma, cudaFuncAttributeMaxDynamicSharedMemorySize,
                         ATTN_SMEM);

    conv16<<<8192, 256>>>(x, Wq, Wk, Wv, Wo);

    dim3 gg(DIM / 128, MROWS / 128);   // (8, 32)
    gemm_hmma<<<gg, 256, GEMM_SMEM>>>(bq, out, 0);
    gemm_hmma<<<gg, 256, GEMM_SMEM>>>(bk, out, 1);
    gemm_hmma<<<gg, 256, GEMM_SMEM>>>(bv, out, 2);

    attn_hmma<<<dim3(SEQ / 64, HEADS, BATCH), 128, ATTN_SMEM>>>(mk);

    gemm_hmma<<<gg, 256, GEMM_SMEM>>>(bo, out, 3);
}